// round 15
// baseline (speedup 1.0000x reference)
#include <cuda_runtime.h>
#include <cuda_fp16.h>
#include <cstdint>

// ---------------------------------------------------------------------------
// Problem constants
// ---------------------------------------------------------------------------
#define BB   128
#define TT   20
#define TS   19
#define NN   49
#define VOCAB 10000
#define NVP  10112       // VOCAB padded to 79*128
#define EMB  512
#define HD   1024
#define VD   512
#define ATT  512
#define G4   4096
#define ZKH  4           // split-K per gates K-half (8 slices total per gate GEMM)
#define ZKT  8           // total slices reduced in lstm_ln
#define WHZ  8           // split-K for wh GEMM

// ---------------------------------------------------------------------------
// fp32 scratch
// ---------------------------------------------------------------------------
#define OFF_VP    ((size_t)0)
#define OFF_UV    (OFF_VP   + (size_t)BB*NN*HD)
#define OFF_FM    (OFF_UV   + (size_t)BB*NN*ATT)
#define OFF_H1    (OFF_FM   + (size_t)BB*HD)
#define OFF_C1    (OFF_H1   + (size_t)2*BB*HD)
#define OFF_C2    (OFF_C1   + (size_t)2*BB*HD)
#define OFF_H2A   (OFF_C2   + (size_t)2*BB*HD)
#define OFF_G1X   (OFF_H2A  + (size_t)TT*BB*HD)
#define OFF_B1    (OFF_G1X  + (size_t)TS*BB*G4)
#define OFF_B2    (OFF_B1   + (size_t)G4)
#define OFF_GP1   (OFF_B2   + (size_t)G4)                  // [8,B,4096]
#define OFF_GP2   (OFF_GP1  + (size_t)ZKT*BB*G4)           // [8,B,4096]
#define OFF_WHP   (OFF_GP2  + (size_t)ZKT*BB*G4)           // [WHZ,B,ATT]
#define OFF_PF    (OFF_WHP  + (size_t)WHZ*BB*ATT)
#define BUF_TOTAL (OFF_PF   + (size_t)TS*BB*EMB)
__device__ float g_buf[BUF_TOTAL];

// ---------------------------------------------------------------------------
// fp16 scratch
// ---------------------------------------------------------------------------
#define SZ_W1   ((size_t)G4*2048)
#define SZ_W2   ((size_t)G4*2048)
#define SZ_EMBW ((size_t)NVP*EMB)
#define SZ_PROJ ((size_t)EMB*HD)
#define SZ_ATTU ((size_t)ATT*HD)
#define SZ_VPW  ((size_t)HD*VD)
#define SZ_WX   ((size_t)G4*EMB)
#define SZ_V    ((size_t)BB*NN*VD)
#define SZ_VPB  ((size_t)BB*NN*HD)
#define SZ_EMBX ((size_t)TS*BB*EMB)
#define SZ_X1   ((size_t)BB*2048)
#define SZ_X2   ((size_t)BB*2048)
#define SZ_H2   ((size_t)TS*BB*HD)
#define SZ_P    ((size_t)TS*BB*EMB)

#define HO_W1   ((size_t)0)
#define HO_W2   (HO_W1   + 2*SZ_W1)
#define HO_EMBW (HO_W2   + 2*SZ_W2)
#define HO_PROJ (HO_EMBW + SZ_EMBW)
#define HO_ATTU (HO_PROJ + 2*SZ_PROJ)
#define HO_VPW  (HO_ATTU + SZ_ATTU)
#define HO_WX   (HO_VPW  + 2*SZ_VPW)
#define HO_V    (HO_WX   + 2*SZ_WX)
#define HO_VPB  (HO_V    + 2*SZ_V)
#define HO_EMBX (HO_VPB  + 2*SZ_VPB)
#define HO_X1   (HO_EMBX + 2*SZ_EMBX)
#define HO_X2   (HO_X1   + 2*SZ_X1)
#define HO_H2   (HO_X2   + 2*SZ_X2)
#define HO_P    (HO_H2   + 2*SZ_H2)
#define HF_TOTAL (HO_P   + SZ_P)
__device__ __half g_hf[HF_TOTAL];

__device__ __forceinline__ float sigf(float x) { return 1.f / (1.f + expf(-x)); }

__device__ __forceinline__ void wr_hl16u(__half* hi, __half* lo, size_t idx, float x) {
    __half h = __float2half(x);
    hi[idx] = h;
    lo[idx] = __float2half(x - __half2float(h));
}

__device__ __forceinline__ uint32_t smem_u32(const void* p) {
    uint32_t a;
    asm("{ .reg .u64 t; cvta.to.shared.u64 t, %1; cvt.u32.u64 %0, t; }" : "=r"(a) : "l"(p));
    return a;
}

// ---------------------------------------------------------------------------
// HMMA primitives (base PTX, sm_80+)
// ---------------------------------------------------------------------------
#define LDSM4(r, a) \
    asm volatile("ldmatrix.sync.aligned.m8n8.x4.shared.b16 {%0,%1,%2,%3}, [%4];" \
        : "=r"((r)[0]), "=r"((r)[1]), "=r"((r)[2]), "=r"((r)[3]) : "r"(a))

#define MMA_F32(d, a, b) \
    asm volatile("mma.sync.aligned.m16n8k16.row.col.f32.f16.f16.f32 " \
        "{%0,%1,%2,%3}, {%4,%5,%6,%7}, {%8,%9}, {%0,%1,%2,%3};" \
        : "+f"((d)[0]), "+f"((d)[1]), "+f"((d)[2]), "+f"((d)[3]) \
        : "r"((a)[0]), "r"((a)[1]), "r"((a)[2]), "r"((a)[3]), \
          "r"((b)[0]), "r"((b)[1]))

__device__ __forceinline__ void cpa16(uint32_t dst, const void* src) {
    asm volatile("cp.async.cg.shared.global [%0], [%1], 16;" :: "r"(dst), "l"(src));
}

// ---------------------------------------------------------------------------
// Pipelined HMMA GEMM (round-14 kernel, unchanged)
// ---------------------------------------------------------------------------
#define SAK 40
#define ARR_BYTES (128 * SAK * 2)
#define HM_SMEM4  (3 * 4 * ARR_BYTES)
#define HM_SMEM3  (3 * 3 * ARR_BYTES)
#define HM_SMEM2  (3 * 2 * ARR_BYTES)

template <int MODE, int BSPL, int ASPL>
__global__ void __launch_bounds__(512, 1)
hmma_gemm(const __half* __restrict__ Ahi, const __half* __restrict__ Alo, int lda,
          const __half* __restrict__ Bhi, const __half* __restrict__ Blo, int ldb,
          float* __restrict__ C, int N, int K,
          const float* __restrict__ bias)
{
    constexpr uint32_t NARR = 2 + ASPL + BSPL;
    constexpr uint32_t STG_BYTES = NARR * ARR_BYTES;
    constexpr uint32_t OF_AL = 1;
    constexpr uint32_t OF_BH = 1 + ASPL;
    constexpr uint32_t OF_BL = 2 + ASPL;

    extern __shared__ __half smh[];
    uint32_t sb = smem_u32(smh);

    const int tid  = threadIdx.x;
    const int lane = tid & 31, wid = tid >> 5;
    const int wm = wid & 3;
    const int wn = wid >> 2;
    const int n0 = blockIdx.x * 128, m0 = blockIdx.y * 128;
    const int kchunk = K / gridDim.z;
    const int kbeg   = blockIdx.z * kchunk;
    const int niter  = kchunk >> 5;

    const int lr = tid >> 2;
    const int lc = (tid & 3) * 8;

    float acc[2][4][4];
#pragma unroll
    for (int i = 0; i < 2; i++)
#pragma unroll
        for (int j = 0; j < 4; j++)
#pragma unroll
            for (int q = 0; q < 4; q++) acc[i][j][q] = 0.f;

    const int arow = wm * 32 + (lane & 15);
    const int acol = (lane >> 4) * 8;
    const int brow = wn * 32 + ((lane >> 4) * 8) + (lane & 7);
    const int bcol = ((lane >> 3) & 1) * 8;
    const uint32_t a_off = (uint32_t)(arow * SAK + acol) * 2;
    const uint32_t b_off = (uint32_t)(brow * SAK + bcol) * 2;

    const uint32_t g_off = (uint32_t)(lr * SAK + lc) * 2;
    const __half* pAh = Ahi + (size_t)(m0 + lr) * lda + lc;
    const __half* pAl = ASPL ? (Alo + (size_t)(m0 + lr) * lda + lc) : nullptr;
    const __half* pBh = Bhi + (size_t)(n0 + lr) * ldb + lc;
    const __half* pBl = BSPL ? (Blo + (size_t)(n0 + lr) * ldb + lc) : nullptr;

#pragma unroll
    for (int pf = 0; pf < 2; pf++) {
        if (pf < niter) {
            const int kb = kbeg + pf * 32;
            uint32_t base = sb + pf * STG_BYTES;
            cpa16(base + 0 * ARR_BYTES + g_off, pAh + kb);
            if (ASPL) cpa16(base + OF_AL * ARR_BYTES + g_off, pAl + kb);
            cpa16(base + OF_BH * ARR_BYTES + g_off, pBh + kb);
            if (BSPL) cpa16(base + OF_BL * ARR_BYTES + g_off, pBl + kb);
            asm volatile("cp.async.commit_group;" ::: "memory");
        }
    }

    int st = 0, pfst = 2;
    for (int it = 0; it < niter; it++) {
        if (it + 2 < niter) {
            const int kb = kbeg + (it + 2) * 32;
            uint32_t base = sb + pfst * STG_BYTES;
            cpa16(base + 0 * ARR_BYTES + g_off, pAh + kb);
            if (ASPL) cpa16(base + OF_AL * ARR_BYTES + g_off, pAl + kb);
            cpa16(base + OF_BH * ARR_BYTES + g_off, pBh + kb);
            if (BSPL) cpa16(base + OF_BL * ARR_BYTES + g_off, pBl + kb);
            asm volatile("cp.async.commit_group;" ::: "memory");
            asm volatile("cp.async.wait_group 2;" ::: "memory");
        } else if (it + 1 < niter) {
            asm volatile("cp.async.wait_group 1;" ::: "memory");
        } else {
            asm volatile("cp.async.wait_group 0;" ::: "memory");
        }
        __syncthreads();

        const uint32_t sbase = sb + st * STG_BYTES;
        const uint32_t a_h = sbase + a_off;
        const uint32_t a_l = sbase + OF_AL * ARR_BYTES + a_off;
        const uint32_t b_h = sbase + OF_BH * ARR_BYTES + b_off;
        const uint32_t b_l = sbase + OF_BL * ARR_BYTES + b_off;

#pragma unroll
        for (int s = 0; s < 2; s++) {
            const uint32_t so = s * 16 * 2;
            uint32_t ah[2][4], al[2][4], bh[4][2], bl[4][2];
#pragma unroll
            for (int mt = 0; mt < 2; mt++) {
                LDSM4(ah[mt], a_h + so + mt * 16 * SAK * 2);
                if (ASPL) LDSM4(al[mt], a_l + so + mt * 16 * SAK * 2);
            }
#pragma unroll
            for (int p = 0; p < 2; p++) {
                uint32_t r4[4];
                LDSM4(r4, b_h + so + p * 16 * SAK * 2);
                bh[p * 2][0] = r4[0]; bh[p * 2][1] = r4[1];
                bh[p * 2 + 1][0] = r4[2]; bh[p * 2 + 1][1] = r4[3];
                if (BSPL) {
                    LDSM4(r4, b_l + so + p * 16 * SAK * 2);
                    bl[p * 2][0] = r4[0]; bl[p * 2][1] = r4[1];
                    bl[p * 2 + 1][0] = r4[2]; bl[p * 2 + 1][1] = r4[3];
                }
            }
#pragma unroll
            for (int mt = 0; mt < 2; mt++)
#pragma unroll
                for (int nt = 0; nt < 4; nt++) {
                    MMA_F32(acc[mt][nt], ah[mt], bh[nt]);
                    if (ASPL) MMA_F32(acc[mt][nt], al[mt], bh[nt]);
                    if (BSPL) MMA_F32(acc[mt][nt], ah[mt], bl[nt]);
                }
        }
        __syncthreads();
        st = (st == 2) ? 0 : st + 1;
        pfst = (pfst == 2) ? 0 : pfst + 1;
    }

    const size_t Mtot = (size_t)gridDim.y * 128;
    float* Cb = C + (gridDim.z > 1 ? (size_t)blockIdx.z * Mtot * N : 0);
    const int er = (lane >> 2);
    const int ec = (lane & 3) * 2;
#pragma unroll
    for (int mt = 0; mt < 2; mt++) {
#pragma unroll
        for (int nt = 0; nt < 4; nt++) {
            int n = n0 + wn * 32 + nt * 8 + ec;
            float b0 = 0.f, b1 = 0.f;
            if (MODE == 0 && bias) { b0 = bias[n]; b1 = bias[n + 1]; }
#pragma unroll
            for (int h = 0; h < 2; h++) {
                int m = m0 + wm * 32 + mt * 16 + er + h * 8;
                float v0 = acc[mt][nt][h * 2 + 0] + b0;
                float v1 = acc[mt][nt][h * 2 + 1] + b1;
                if (MODE == 0) {
                    *(float2*)&Cb[(size_t)m * N + n] = make_float2(v0, v1);
                } else {
                    int b = m & 127, t = m >> 7;
                    float* o = &Cb[((size_t)b * TS + t) * VOCAB + n];
                    if (n < VOCAB) o[0] = v0;
                    if (n + 1 < VOCAB) o[1] = v1;
                }
            }
        }
    }
}

// ---------------------------------------------------------------------------
// fp32 SGEMM (small: ih/ic init, per-step wh) — f32x2
// ---------------------------------------------------------------------------
__device__ __forceinline__ void fma2(unsigned long long& d, unsigned long long a,
                                     unsigned long long b) {
    asm("fma.rn.f32x2 %0, %1, %2, %0;" : "+l"(d) : "l"(a), "l"(b));
}
__device__ __forceinline__ unsigned long long splat2(float x) {
    unsigned long long r;
    unsigned u = __float_as_uint(x);
    asm("mov.b64 %0, {%1, %1};" : "=l"(r) : "r"(u));
    return r;
}

template <int MODE>
__global__ void __launch_bounds__(128)
gemm_tile(const float* __restrict__ A, int lda,
          const float* __restrict__ W, int ldw,
          float* __restrict__ C, int N, int K,
          const float* __restrict__ bias)
{
    __shared__ float As[32][132];
    __shared__ float Ws[32][36];
    const int tid = threadIdx.x;
    const int n0 = blockIdx.x * 32, m0 = blockIdx.y * 128;
    const int kchunk = K / gridDim.z;
    const int kbeg = blockIdx.z * kchunk;
    const float* Ab = A + (size_t)m0 * lda;
    const int a_c = tid & 7, a_r = tid >> 3;
    const int ty = tid >> 3, tx = tid & 7;

    unsigned long long acc[4][4];
#pragma unroll
    for (int i = 0; i < 4; i++)
#pragma unroll
        for (int j = 0; j < 4; j++) acc[i][j] = 0ull;

    for (int kb = kbeg; kb < kbeg + kchunk; kb += 32) {
#pragma unroll
        for (int i = 0; i < 8; i++) {
            int r = a_r + 16 * i;
            float4 v = *reinterpret_cast<const float4*>(Ab + (size_t)r * lda + kb + 4 * a_c);
            As[4 * a_c + 0][r] = v.x; As[4 * a_c + 1][r] = v.y;
            As[4 * a_c + 2][r] = v.z; As[4 * a_c + 3][r] = v.w;
        }
#pragma unroll
        for (int i = 0; i < 2; i++) {
            int idx = tid + 128 * i;
            int r = idx >> 3, c = idx & 7;
            int n = n0 + r;
            float4 v = make_float4(0.f, 0.f, 0.f, 0.f);
            if (n < N) v = *reinterpret_cast<const float4*>(W + (size_t)n * ldw + kb + 4 * c);
            Ws[4 * c + 0][r] = v.x; Ws[4 * c + 1][r] = v.y;
            Ws[4 * c + 2][r] = v.z; Ws[4 * c + 3][r] = v.w;
        }
        __syncthreads();
#pragma unroll
        for (int kk = 0; kk < 32; kk++) {
            double2 a01 = *reinterpret_cast<const double2*>(&As[kk][ty * 8]);
            double2 a23 = *reinterpret_cast<const double2*>(&As[kk][ty * 8 + 4]);
            unsigned long long av[4] = {__double_as_longlong(a01.x), __double_as_longlong(a01.y),
                                        __double_as_longlong(a23.x), __double_as_longlong(a23.y)};
            float4 w = *reinterpret_cast<const float4*>(&Ws[kk][tx * 4]);
            unsigned long long wv[4] = {splat2(w.x), splat2(w.y), splat2(w.z), splat2(w.w)};
#pragma unroll
            for (int i = 0; i < 4; i++)
#pragma unroll
                for (int j = 0; j < 4; j++) fma2(acc[i][j], av[i], wv[j]);
        }
        __syncthreads();
    }

    const size_t Mtot = (size_t)gridDim.y * 128;
    float* Cb = C + (gridDim.z > 1 ? (size_t)blockIdx.z * Mtot * N : 0);
#pragma unroll
    for (int i = 0; i < 4; i++) {
        int mA = m0 + ty * 8 + 2 * i;
#pragma unroll
        for (int j = 0; j < 4; j++) {
            int n = n0 + tx * 4 + j;
            if (n >= N) continue;
            float2 p = *reinterpret_cast<float2*>(&acc[i][j]);
            float v0 = p.x, v1 = p.y;
            if (MODE == 1) { v0 = tanhf(v0 + bias[n]); v1 = tanhf(v1 + bias[n]); }
            else if (bias) { v0 += bias[n]; v1 += bias[n]; }
            Cb[(size_t)mA * N + n] = v0;
            Cb[(size_t)(mA + 1) * N + n] = v1;
        }
    }
}

// ---------------------------------------------------------------------------
// Prep / conversion kernels
// ---------------------------------------------------------------------------
#define NB_WX   8192
#define NB_V    12544
#define NB_EMBX 4864
#define NB_VPW  2048
#define NB_MEGA (NB_WX + NB_V + NB_EMBX + NB_VPW)

__global__ void mega_cvt4(const float* __restrict__ l1_Wih,
                          const float* __restrict__ V,
                          const float* __restrict__ embW,
                          const int* __restrict__ y,
                          const float* __restrict__ Vp_W,
                          __half* __restrict__ WXh, __half* __restrict__ WXl,
                          __half* __restrict__ Vh,  __half* __restrict__ Vl,
                          __half* __restrict__ EXh, __half* __restrict__ EXl,
                          __half* __restrict__ VWh, __half* __restrict__ VWl)
{
    int bid = blockIdx.x;
    if (bid < NB_WX) {
        int idx = bid * 256 + threadIdx.x;
        int r = idx >> 9, c = idx & 511;
        wr_hl16u(WXh, WXl, idx, l1_Wih[(size_t)r * 1536 + c]);
    } else if (bid < NB_WX + NB_V) {
        int idx = (bid - NB_WX) * 256 + threadIdx.x;
        wr_hl16u(Vh, Vl, idx, V[idx]);
    } else if (bid < NB_WX + NB_V + NB_EMBX) {
        int idx = (bid - NB_WX - NB_V) * 256 + threadIdx.x;
        int e = idx & 511;
        int b = (idx >> 9) & 127;
        int t = idx >> 16;
        wr_hl16u(EXh, EXl, idx, embW[(size_t)y[b * TT + t] * EMB + e]);
    } else {
        int idx = (bid - NB_WX - NB_V - NB_EMBX) * 256 + threadIdx.x;
        wr_hl16u(VWh, VWl, idx, Vp_W[idx]);
    }
}

__global__ void cvt_hl(const float* __restrict__ src, int ld, int rows, int cols,
                       __half* __restrict__ hi, __half* __restrict__ lo, int rowsPad)
{
    int idx = blockIdx.x * 256 + threadIdx.x;
    if (idx >= rowsPad * cols) return;
    int r = idx / cols, c = idx - r * cols;
    float x = (r < rows) ? src[(size_t)r * ld + c] : 0.f;
    wr_hl16u(hi, lo, idx, x);
}

__global__ void cvt_h(const float* __restrict__ src, int ld, int rows, int cols,
                      __half* __restrict__ dst, int rowsPad)
{
    int idx = blockIdx.x * 256 + threadIdx.x;
    if (idx >= rowsPad * cols) return;
    int r = idx / cols, c = idx - r * cols;
    float x = (r < rows) ? src[(size_t)r * ld + c] : 0.f;
    dst[idx] = __float2half(x);
}

// H1 slot0 -> X1 h-half hi/lo (pointers pre-offset by +1024)
__global__ void cvt_h1x1(const float* __restrict__ h1,
                         __half* __restrict__ xh, __half* __restrict__ xl)
{
    int idx = blockIdx.x * 256 + threadIdx.x;
    if (idx >= BB * HD) return;
    int b = idx >> 10, h = idx & 1023;
    wr_hl16u(xh, xl, (size_t)b * 2048 + h, h1[idx]);
}

__global__ void build_wcat_hl(__half* __restrict__ hi, __half* __restrict__ lo,
                              const float* __restrict__ Wih, int ld_ih, int coff,
                              const float* __restrict__ Whh)
{
    int idx = blockIdx.x * 256 + threadIdx.x;
    if (idx >= G4 * 2048) return;
    int n = idx >> 11, k = idx & 2047;
    float x = (k < 1024) ? Wih[(size_t)n * ld_ih + coff + k]
                         : Whh[(size_t)n * 1024 + (k - 1024)];
    wr_hl16u(hi, lo, idx, x);
}

__global__ void add_bias_kernel(float* __restrict__ dst, const float* __restrict__ a,
                                const float* __restrict__ b, int n)
{
    int i = blockIdx.x * 256 + threadIdx.x;
    if (i < n) dst[i] = a[i] + b[i];
}

__global__ void feat_mean_kernel(const float* __restrict__ Vp, float* __restrict__ fm)
{
    int idx = blockIdx.x * 256 + threadIdx.x;
    if (idx >= BB * HD) return;
    int b = idx >> 10, h = idx & 1023;
    const float* p = Vp + (size_t)b * NN * HD + h;
    float s = 0.f;
#pragma unroll 7
    for (int n = 0; n < NN; n++) s += p[n * HD];
    fm[idx] = s * (1.f / 49.f);
}

// ---------------------------------------------------------------------------
// Attention: sums WHZ wh partials, warp softmax, ctx -> X1 ctx-half hi/lo
// ---------------------------------------------------------------------------
__global__ void attn_kernel(const float* __restrict__ Vp, const float* __restrict__ Uv,
                            const float* __restrict__ whp, const float* __restrict__ attv,
                            __half* __restrict__ x1h, __half* __restrict__ x1l)
{
    int b = blockIdx.x, tid = threadIdx.x;
    __shared__ float s_wh[ATT];
    __shared__ float s_e[NN];

    for (int a = tid; a < ATT; a += 256) {
        int o = b * ATT + a;
        float s = 0.f;
#pragma unroll
        for (int z = 0; z < WHZ; z++) s += whp[z * BB * ATT + o];
        s_wh[a] = s;
    }
    __syncthreads();

    int warp = tid >> 5, lane = tid & 31;
    for (int n = warp; n < NN; n += 8) {
        const float* uv = Uv + ((size_t)b * NN + n) * ATT;
        float s = 0.f;
        for (int a = lane; a < ATT; a += 32) s += tanhf(s_wh[a] + uv[a]) * attv[a];
#pragma unroll
        for (int o = 16; o > 0; o >>= 1) s += __shfl_down_sync(0xffffffffu, s, o);
        if (lane == 0) s_e[n] = s;
    }
    __syncthreads();

    if (warp == 0) {
        float m = -1e30f;
        for (int n = lane; n < NN; n += 32) m = fmaxf(m, s_e[n]);
#pragma unroll
        for (int o = 16; o > 0; o >>= 1) m = fmaxf(m, __shfl_xor_sync(0xffffffffu, m, o));
        float S = 0.f;
        float v0 = 0.f, v1 = 0.f;
        if (lane < NN) { v0 = expf(s_e[lane] - m); S += v0; }
        if (lane + 32 < NN) { v1 = expf(s_e[lane + 32] - m); S += v1; }
#pragma unroll
        for (int o = 16; o > 0; o >>= 1) S += __shfl_xor_sync(0xffffffffu, S, o);
        float inv = 1.f / S;
        if (lane < NN) s_e[lane] = v0 * inv;
        if (lane + 32 < NN) s_e[lane + 32] = v1 * inv;
    }
    __syncthreads();

    const float* vpb = Vp + (size_t)b * NN * HD;
    for (int h = tid; h < HD; h += 256) {
        float acc = 0.f;
#pragma unroll 7
        for (int n = 0; n < NN; n++) acc += s_e[n] * vpb[n * HD + h];
        wr_hl16u(x1h, x1l, (size_t)b * 2048 + h, acc);
    }
}

// ---------------------------------------------------------------------------
// LSTM cell + LN fused; reduces ZKT=8 partial slices. LN output written to:
// hout (fp32), xA hi/lo (required, pre-offset), xB hi/lo (optional, pre-offset)
// ---------------------------------------------------------------------------
__global__ void __launch_bounds__(512)
lstm_ln_kernel(const float* __restrict__ gp, const float* __restrict__ bias,
               const float* __restrict__ extra,
               const float* __restrict__ cin, float* __restrict__ cout,
               const float* __restrict__ gam, const float* __restrict__ bet,
               float* __restrict__ hout,
               __half* __restrict__ xAh, __half* __restrict__ xAl,
               __half* __restrict__ xBh, __half* __restrict__ xBl)
{
    const size_t BG = (size_t)BB * G4;
    int b = blockIdx.x, tid = threadIdx.x;
    __shared__ float s_h[HD];
    __shared__ float s_red[64];
    __shared__ float s_mu, s_rstd;

    float sum = 0.f, sq = 0.f;
    for (int h = tid; h < HD; h += 512) {
        float g[4];
#pragma unroll
        for (int q = 0; q < 4; q++) {
            size_t idx = (size_t)b * G4 + q * 1024 + h;
            float v = bias[q * 1024 + h];
#pragma unroll
            for (int z = 0; z < ZKT; z++) v += gp[z * BG + idx];
            if (extra) v += extra[idx];
            g[q] = v;
        }
        float c = sigf(g[1]) * cin[b * HD + h] + sigf(g[0]) * tanhf(g[2]);
        cout[b * HD + h] = c;
        float hv = sigf(g[3]) * tanhf(c);
        s_h[h] = hv;
        sum += hv; sq += hv * hv;
    }
#pragma unroll
    for (int o = 16; o > 0; o >>= 1) {
        sum += __shfl_down_sync(0xffffffffu, sum, o);
        sq  += __shfl_down_sync(0xffffffffu, sq,  o);
    }
    int warp = tid >> 5, lane = tid & 31;
    if (lane == 0) { s_red[warp] = sum; s_red[32 + warp] = sq; }
    __syncthreads();
    if (tid == 0) {
        float S = 0.f, Q = 0.f;
        for (int w = 0; w < 16; w++) { S += s_red[w]; Q += s_red[32 + w]; }
        float mu = S * (1.f / 1024.f);
        float var = Q * (1.f / 1024.f) - mu * mu;
        s_mu = mu; s_rstd = 1.f / sqrtf(var + 1e-5f);
    }
    __syncthreads();
    float mu = s_mu, rstd = s_rstd;
    for (int h = tid; h < HD; h += 512) {
        float v = (s_h[h] - mu) * rstd * gam[h] + bet[h];
        hout[b * HD + h] = v;
        wr_hl16u(xAh, xAl, (size_t)b * 2048 + h, v);
        if (xBh) wr_hl16u(xBh, xBl, (size_t)b * 2048 + h, v);
    }
}

// ---------------------------------------------------------------------------
// Launch
// ---------------------------------------------------------------------------
extern "C" void kernel_launch(void* const* d_in, const int* in_sizes, int n_in,
                              void* d_out, int out_size)
{
    (void)in_sizes; (void)n_in; (void)out_size;
    const float* V      = (const float*)d_in[0];
    const int*   y      = (const int*)  d_in[1];
    const float* embW   = (const float*)d_in[2];
    const float* Vp_W   = (const float*)d_in[3];
    const float* Vp_b   = (const float*)d_in[4];
    const float* attW   = (const float*)d_in[5];
    const float* attU   = (const float*)d_in[6];
    const float* attv   = (const float*)d_in[7];
    const float* l1_Wih = (const float*)d_in[8];
    const float* l1_Whh = (const float*)d_in[9];
    const float* l1_bih = (const float*)d_in[10];
    const float* l1_bhh = (const float*)d_in[11];
    const float* l2_Wih = (const float*)d_in[12];
    const float* l2_Whh = (const float*)d_in[13];
    const float* l2_bih = (const float*)d_in[14];
    const float* l2_bhh = (const float*)d_in[15];
    const float* n1_g   = (const float*)d_in[16];
    const float* n1_b   = (const float*)d_in[17];
    const float* n2_g   = (const float*)d_in[18];
    const float* n2_b   = (const float*)d_in[19];
    const float* ih_W   = (const float*)d_in[20];
    const float* ih_b   = (const float*)d_in[21];
    const float* ic_W   = (const float*)d_in[22];
    const float* ic_b   = (const float*)d_in[23];
    const float* proj_W = (const float*)d_in[24];
    float* out = (float*)d_out;

    cudaFuncSetAttribute(hmma_gemm<0, 1, 1>, cudaFuncAttributeMaxDynamicSharedMemorySize, HM_SMEM4);
    cudaFuncSetAttribute(hmma_gemm<0, 0, 1>, cudaFuncAttributeMaxDynamicSharedMemorySize, HM_SMEM3);
    cudaFuncSetAttribute(hmma_gemm<3, 0, 0>, cudaFuncAttributeMaxDynamicSharedMemorySize, HM_SMEM2);

    float* buf = nullptr;
    cudaGetSymbolAddress((void**)&buf, g_buf);
    __half* hf = nullptr;
    cudaGetSymbolAddress((void**)&hf, g_hf);

    float* VP  = buf + OFF_VP;
    float* UV  = buf + OFF_UV;
    float* FM  = buf + OFF_FM;
    float* H1  = buf + OFF_H1;
    float* C1  = buf + OFF_C1;
    float* C2  = buf + OFF_C2;
    float* H2A = buf + OFF_H2A;
    float* G1X = buf + OFF_G1X;
    float* B1  = buf + OFF_B1;
    float* B2  = buf + OFF_B2;
    float* GP1 = buf + OFF_GP1;
    float* GP2 = buf + OFF_GP2;
    float* WHP = buf + OFF_WHP;
    float* PF  = buf + OFF_PF;
    float* GP1H = GP1 + (size_t)4 * BB * G4;   // h-half slices 4..7
    float* GP2H = GP2 + (size_t)4 * BB * G4;

    __half *W1h = hf + HO_W1,   *W1l = W1h + SZ_W1;
    __half *W2h = hf + HO_W2,   *W2l = W2h + SZ_W2;
    __half *EWs = hf + HO_EMBW;
    __half *PJh = hf + HO_PROJ, *PJl = PJh + SZ_PROJ;
    __half *AUs = hf + HO_ATTU;
    __half *VWh = hf + HO_VPW,  *VWl = VWh + SZ_VPW;
    __half *WXh = hf + HO_WX,   *WXl = WXh + SZ_WX;
    __half *Vh  = hf + HO_V,    *Vl  = Vh  + SZ_V;
    __half *VPh = hf + HO_VPB,  *VPl = VPh + SZ_VPB;
    __half *EXh = hf + HO_EMBX, *EXl = EXh + SZ_EMBX;
    __half *X1h = hf + HO_X1,   *X1l = X1h + SZ_X1;
    __half *X2h = hf + HO_X2,   *X2l = X2h + SZ_X2;
    __half *H2h = hf + HO_H2,   *H2l = H2h + SZ_H2;
    __half *Ps  = hf + HO_P;

    const int SLOT = BB * HD;
    auto nb = [](size_t tot) { return (unsigned)((tot + 255) / 256); };

    // side stream + events for gates h-half overlap (created per call; leaked —
    // kernel_launch runs only for correctness + capture, never in the timed loop)
    cudaStream_t sB;
    cudaStreamCreateWithFlags(&sB, cudaStreamNonBlocking);
    cudaEvent_t eL1, eL2, eG1, eG2;
    cudaEventCreateWithFlags(&eL1, cudaEventDisableTiming);
    cudaEventCreateWithFlags(&eL2, cudaEventDisableTiming);
    cudaEventCreateWithFlags(&eG1, cudaEventDisableTiming);
    cudaEventCreateWithFlags(&eG2, cudaEventDisableTiming);

    // ---- prologue ----
    mega_cvt4<<<NB_MEGA, 256>>>(l1_Wih, V, embW, y, Vp_W,
                                WXh, WXl, Vh, Vl, EXh, EXl, VWh, VWl);
    hmma_gemm<0, 1, 1><<<dim3(G4 / 128, 10, 1), 512, HM_SMEM4>>>(EXh, EXl, EMB, WXh, WXl, EMB,
                                                                 G1X, G4, EMB, nullptr);
    hmma_gemm<0, 1, 1><<<dim3(G4 / 128, 9, 1), 512, HM_SMEM4>>>(EXh + (size_t)1280 * EMB,
                                                                EXl + (size_t)1280 * EMB, EMB,
                                                                WXh, WXl, EMB,
                                                                G1X + (size_t)1280 * G4, G4, EMB,
                                                                nullptr);
    hmma_gemm<0, 1, 1><<<dim3(HD / 128, NN, 1), 512, HM_SMEM4>>>(Vh, Vl, VD, VWh, VWl, VD,
                                                                 VP, HD, VD, Vp_b);

    build_wcat_hl<<<nb((size_t)G4 * 2048), 256>>>(W1h, W1l, l1_Wih, 1536, 512, l1_Whh);
    build_wcat_hl<<<nb((size_t)G4 * 2048), 256>>>(W2h, W2l, l2_Wih, 1024, 0, l2_Whh);
    cvt_h<<<nb((size_t)NVP * EMB), 256>>>(embW, EMB, VOCAB, EMB, EWs, NVP);
    cvt_hl<<<nb(SZ_PROJ), 256>>>(proj_W, HD, EMB, HD, PJh, PJl, EMB);
    cvt_h<<<nb(SZ_ATTU), 256>>>(attU, HD, ATT, HD, AUs, ATT);
    add_bias_kernel<<<32, 256>>>(B1, l1_bih, l1_bhh, G4);
    add_bias_kernel<<<32, 256>>>(B2, l2_bih, l2_bhh, G4);

    cvt_hl<<<nb(SZ_VPB), 256>>>(VP, HD, BB * NN, HD, VPh, VPl, BB * NN);
    feat_mean_kernel<<<nb((size_t)BB * HD), 256>>>(VP, FM);
    gemm_tile<1><<<dim3(HD / 32, 1, 1), 128>>>(FM, HD, ih_W, HD, H1, HD, HD, ih_b);
    gemm_tile<1><<<dim3(HD / 32, 1, 1), 128>>>(FM, HD, ic_W, HD, C1, HD, HD, ic_b);
    hmma_gemm<0, 0, 1><<<dim3(ATT / 128, NN, 1), 512, HM_SMEM3>>>(VPh, VPl, HD, AUs, nullptr,
                                                                  HD, UV, ATT, HD, nullptr);

    cudaMemsetAsync(H2A, 0, (size_t)SLOT * sizeof(float), 0);
    cudaMemsetAsync(C2, 0, (size_t)SLOT * sizeof(float), 0);
    // X2 (both hi and lo) = 0 so X2 h2-half is h2(0)=0; lstm1(0) fills h1n half
    cudaMemsetAsync(X2h, 0, 2 * SZ_X2 * sizeof(__half), 0);
    // GP2 h-half slices = 0 for t=0 (h2(0)=0 -> contribution 0)
    cudaMemsetAsync(GP2H, 0, (size_t)4 * BB * G4 * sizeof(float), 0);
    // X1 h-half = h1(0)
    cvt_h1x1<<<nb((size_t)BB * HD), 256>>>(H1, X1h + 1024, X1l + 1024);
    // g1h(0): W1_hh @ h1(0) -> GP1 slices 4..7 (main stream, pre-loop)
    hmma_gemm<0, 1, 1><<<dim3(G4 / 128, 1, ZKH), 512, HM_SMEM4>>>(
        X1h + 1024, X1l + 1024, 2048, W1h + 1024, W1l + 1024, 2048,
        GP1H, G4, 1024, nullptr);

    // ---- sequential decode with forked gates h-halves ----
    for (int t = 0; t < TS; t++) {
        const float* h2c = H2A + (size_t)t * SLOT;
        gemm_tile<0><<<dim3(ATT / 32, 1, WHZ), 128>>>(h2c, HD, attW, HD, WHP, ATT, HD, nullptr);
        attn_kernel<<<BB, 256>>>(VP, UV, WHP, attv, X1h, X1l);
        // gates1 ctx-half -> GP1 slices 0..3
        hmma_gemm<0, 1, 1><<<dim3(G4 / 128, 1, ZKH), 512, HM_SMEM4>>>(
            X1h, X1l, 2048, W1h, W1l, 2048, GP1, G4, 1024, nullptr);
        if (t > 0) cudaStreamWaitEvent(0, eG1, 0);
        lstm_ln_kernel<<<BB, 512>>>(GP1, B1, G1X + (size_t)t * BB * G4,
                                    C1 + (size_t)(t & 1) * SLOT,
                                    C1 + (size_t)((t + 1) & 1) * SLOT,
                                    n1_g, n1_b, H1 + (size_t)((t + 1) & 1) * SLOT,
                                    X1h + 1024, X1l + 1024,   // h1 for next step
                                    X2h, X2l);                // h1n for gates2 now
        cudaEventRecord(eL1, 0);
        if (t + 1 < TS) {
            cudaStreamWaitEvent(sB, eL1, 0);
            hmma_gemm<0, 1, 1><<<dim3(G4 / 128, 1, ZKH), 512, HM_SMEM4, sB>>>(
                X1h + 1024, X1l + 1024, 2048, W1h + 1024, W1l + 1024, 2048,
                GP1H, G4, 1024, nullptr);
            cudaEventRecord(eG1, sB);
        }
        // gates2 h1n-half -> GP2 slices 0..3
        hmma_gemm<0, 1, 1><<<dim3(G4 / 128, 1, ZKH), 512, HM_SMEM4>>>(
            X2h, X2l, 2048, W2h, W2l, 2048, GP2, G4, 1024, nullptr);
        if (t > 0) cudaStreamWaitEvent(0, eG2, 0);
        lstm_ln_kernel<<<BB, 512>>>(GP2, B2, nullptr,
                                    C2 + (size_t)(t & 1) * SLOT,
                                    C2 + (size_t)((t + 1) & 1) * SLOT,
                                    n2_g, n2_b, H2A + (size_t)(t + 1) * SLOT,
                                    X2h + 1024, X2l + 1024,   // h2 for next step
                                    nullptr, nullptr);
        cudaEventRecord(eL2, 0);
        if (t + 1 < TS) {
            cudaStreamWaitEvent(sB, eL2, 0);
            hmma_gemm<0, 1, 1><<<dim3(G4 / 128, 1, ZKH), 512, HM_SMEM4, sB>>>(
                X2h + 1024, X2l + 1024, 2048, W2h + 1024, W2l + 1024, 2048,
                GP2H, G4, 1024, nullptr);
            cudaEventRecord(eG2, sB);
        }
    }

    // ---- deferred output projection (proj 3-pass, logits 1-pass) ----
    cvt_hl<<<nb(SZ_H2), 256>>>(H2A + SLOT, HD, TS * BB, HD, H2h, H2l, TS * BB);
    hmma_gemm<0, 1, 1><<<dim3(EMB / 128, TS, 1), 512, HM_SMEM4>>>(H2h, H2l, HD, PJh, PJl, HD,
                                                                  PF, EMB, HD, nullptr);
    cvt_h<<<nb(SZ_P), 256>>>(PF, EMB, TS * BB, EMB, Ps, TS * BB);
    hmma_gemm<3, 0, 0><<<dim3(NVP / 128, TS, 1), 512, HM_SMEM2>>>(Ps, nullptr, EMB, EWs, nullptr,
                                                                  EMB, out, VOCAB, EMB, nullptr);
}

// round 16
// speedup vs baseline: 1.1753x; 1.1753x over previous
#include <cuda_runtime.h>
#include <cuda_fp16.h>
#include <cstdint>

// ---------------------------------------------------------------------------
// Problem constants
// ---------------------------------------------------------------------------
#define BB   128
#define TT   20
#define TS   19
#define NN   49
#define VOCAB 10000
#define NVP  10112       // VOCAB padded to 79*128
#define EMB  512
#define HD   1024
#define VD   512
#define ATT  512
#define G4   4096
#define ZK   4           // split-K for sequential gates GEMMs
#define WHZ  8           // split-K for wh GEMM

// ---------------------------------------------------------------------------
// fp32 scratch
// ---------------------------------------------------------------------------
#define OFF_VP    ((size_t)0)
#define OFF_UV    (OFF_VP   + (size_t)BB*NN*HD)
#define OFF_FM    (OFF_UV   + (size_t)BB*NN*ATT)
#define OFF_H1    (OFF_FM   + (size_t)BB*HD)
#define OFF_C1    (OFF_H1   + (size_t)2*BB*HD)
#define OFF_C2    (OFF_C1   + (size_t)2*BB*HD)
#define OFF_H2A   (OFF_C2   + (size_t)2*BB*HD)
#define OFF_G1X   (OFF_H2A  + (size_t)TT*BB*HD)
#define OFF_B1    (OFF_G1X  + (size_t)TS*BB*G4)
#define OFF_B2    (OFF_B1   + (size_t)G4)
#define OFF_GP    (OFF_B2   + (size_t)G4)                  // [ZK,B,4096]
#define OFF_WHP   (OFF_GP   + (size_t)ZK*BB*G4)            // [WHZ,B,ATT]
#define OFF_PF    (OFF_WHP  + (size_t)WHZ*BB*ATT)
#define BUF_TOTAL (OFF_PF   + (size_t)TS*BB*EMB)
__device__ float g_buf[BUF_TOTAL];

// ---------------------------------------------------------------------------
// fp16 scratch
// ---------------------------------------------------------------------------
#define SZ_W1   ((size_t)G4*2048)
#define SZ_W2   ((size_t)G4*2048)
#define SZ_EMBW ((size_t)NVP*EMB)
#define SZ_PROJ ((size_t)EMB*HD)
#define SZ_ATTU ((size_t)ATT*HD)
#define SZ_VPW  ((size_t)HD*VD)
#define SZ_WX   ((size_t)G4*EMB)
#define SZ_V    ((size_t)BB*NN*VD)
#define SZ_VPB  ((size_t)BB*NN*HD)
#define SZ_EMBX ((size_t)TS*BB*EMB)
#define SZ_X1   ((size_t)BB*2048)
#define SZ_X2   ((size_t)BB*2048)
#define SZ_H2   ((size_t)TS*BB*HD)
#define SZ_P    ((size_t)TS*BB*EMB)

#define HO_W1   ((size_t)0)
#define HO_W2   (HO_W1   + 2*SZ_W1)
#define HO_EMBW (HO_W2   + 2*SZ_W2)
#define HO_PROJ (HO_EMBW + SZ_EMBW)
#define HO_ATTU (HO_PROJ + 2*SZ_PROJ)
#define HO_VPW  (HO_ATTU + SZ_ATTU)
#define HO_WX   (HO_VPW  + 2*SZ_VPW)
#define HO_V    (HO_WX   + 2*SZ_WX)
#define HO_VPB  (HO_V    + 2*SZ_V)
#define HO_EMBX (HO_VPB  + SZ_VPB)
#define HO_X1   (HO_EMBX + 2*SZ_EMBX)
#define HO_X2   (HO_X1   + 2*SZ_X1)
#define HO_H2   (HO_X2   + 2*SZ_X2)
#define HO_P    (HO_H2   + 2*SZ_H2)
#define HF_TOTAL (HO_P   + SZ_P)
__device__ __half g_hf[HF_TOTAL];

__device__ __forceinline__ float sigf(float x) { return 1.f / (1.f + expf(-x)); }

// unscaled fp16 hi/lo split: x ~= hi + lo  (captures ~22 mantissa bits)
__device__ __forceinline__ void wr_hl16u(__half* hi, __half* lo, size_t idx, float x) {
    __half h = __float2half(x);
    hi[idx] = h;
    lo[idx] = __float2half(x - __half2float(h));
}

__device__ __forceinline__ uint32_t smem_u32(const void* p) {
    uint32_t a;
    asm("{ .reg .u64 t; cvta.to.shared.u64 t, %1; cvt.u32.u64 %0, t; }" : "=r"(a) : "l"(p));
    return a;
}

// ---------------------------------------------------------------------------
// HMMA primitives (base PTX, sm_80+)
// ---------------------------------------------------------------------------
#define LDSM4(r, a) \
    asm volatile("ldmatrix.sync.aligned.m8n8.x4.shared.b16 {%0,%1,%2,%3}, [%4];" \
        : "=r"((r)[0]), "=r"((r)[1]), "=r"((r)[2]), "=r"((r)[3]) : "r"(a))

#define MMA_F32(d, a, b) \
    asm volatile("mma.sync.aligned.m16n8k16.row.col.f32.f16.f16.f32 " \
        "{%0,%1,%2,%3}, {%4,%5,%6,%7}, {%8,%9}, {%0,%1,%2,%3};" \
        : "+f"((d)[0]), "+f"((d)[1]), "+f"((d)[2]), "+f"((d)[3]) \
        : "r"((a)[0]), "r"((a)[1]), "r"((a)[2]), "r"((a)[3]), \
          "r"((b)[0]), "r"((b)[1]))

__device__ __forceinline__ void cpa16(uint32_t dst, const void* src) {
    asm volatile("cp.async.cg.shared.global [%0], [%1], 16;" :: "r"(dst), "l"(src));
}

// ---------------------------------------------------------------------------
// Pipelined HMMA GEMM: C[M,N] = A[M,K] @ B[N,K]^T, fp16 unscaled hi/lo.
// ASPL: A split (adds Al*Bh pass). BSPL: B split (adds Ah*Bl pass).
// BM=128, BN=128, BK=32, 512 threads (4x4 warps, warp tile 32x32).
// 3-stage cp.async pipeline.
// MODE 0: fp32 store (+bias), splitK z partials.  MODE 3: logits permuted store.
// ---------------------------------------------------------------------------
#define SAK 40
#define ARR_BYTES (128 * SAK * 2)         // 10240
#define HM_SMEM4  (3 * 4 * ARR_BYTES)     // 122880 (3-pass)
#define HM_SMEM2  (3 * 2 * ARR_BYTES)     // 61440  (1-pass)

template <int MODE, int BSPL, int ASPL>
__global__ void __launch_bounds__(512, 1)
hmma_gemm(const __half* __restrict__ Ahi, const __half* __restrict__ Alo, int lda,
          const __half* __restrict__ Bhi, const __half* __restrict__ Blo, int ldb,
          float* __restrict__ C, int N, int K,
          const float* __restrict__ bias)
{
    constexpr uint32_t NARR = 2 + ASPL + BSPL;
    constexpr uint32_t STG_BYTES = NARR * ARR_BYTES;
    constexpr uint32_t OF_AL = 1;
    constexpr uint32_t OF_BH = 1 + ASPL;
    constexpr uint32_t OF_BL = 2 + ASPL;

    extern __shared__ __half smh[];
    uint32_t sb = smem_u32(smh);

    const int tid  = threadIdx.x;
    const int lane = tid & 31, wid = tid >> 5;
    const int wm = wid & 3;
    const int wn = wid >> 2;
    const int n0 = blockIdx.x * 128, m0 = blockIdx.y * 128;
    const int kchunk = K / gridDim.z;
    const int kbeg   = blockIdx.z * kchunk;
    const int niter  = kchunk >> 5;

    const int lr = tid >> 2;
    const int lc = (tid & 3) * 8;

    float acc[2][4][4];
#pragma unroll
    for (int i = 0; i < 2; i++)
#pragma unroll
        for (int j = 0; j < 4; j++)
#pragma unroll
            for (int q = 0; q < 4; q++) acc[i][j][q] = 0.f;

    const int arow = wm * 32 + (lane & 15);
    const int acol = (lane >> 4) * 8;
    const int brow = wn * 32 + ((lane >> 4) * 8) + (lane & 7);
    const int bcol = ((lane >> 3) & 1) * 8;
    const uint32_t a_off = (uint32_t)(arow * SAK + acol) * 2;
    const uint32_t b_off = (uint32_t)(brow * SAK + bcol) * 2;

    const uint32_t g_off = (uint32_t)(lr * SAK + lc) * 2;
    const __half* pAh = Ahi + (size_t)(m0 + lr) * lda + lc;
    const __half* pAl = ASPL ? (Alo + (size_t)(m0 + lr) * lda + lc) : nullptr;
    const __half* pBh = Bhi + (size_t)(n0 + lr) * ldb + lc;
    const __half* pBl = BSPL ? (Blo + (size_t)(n0 + lr) * ldb + lc) : nullptr;

#pragma unroll
    for (int pf = 0; pf < 2; pf++) {
        if (pf < niter) {
            const int kb = kbeg + pf * 32;
            uint32_t base = sb + pf * STG_BYTES;
            cpa16(base + 0 * ARR_BYTES + g_off, pAh + kb);
            if (ASPL) cpa16(base + OF_AL * ARR_BYTES + g_off, pAl + kb);
            cpa16(base + OF_BH * ARR_BYTES + g_off, pBh + kb);
            if (BSPL) cpa16(base + OF_BL * ARR_BYTES + g_off, pBl + kb);
            asm volatile("cp.async.commit_group;" ::: "memory");
        }
    }

    int st = 0, pfst = 2;
    for (int it = 0; it < niter; it++) {
        if (it + 2 < niter) {
            const int kb = kbeg + (it + 2) * 32;
            uint32_t base = sb + pfst * STG_BYTES;
            cpa16(base + 0 * ARR_BYTES + g_off, pAh + kb);
            if (ASPL) cpa16(base + OF_AL * ARR_BYTES + g_off, pAl + kb);
            cpa16(base + OF_BH * ARR_BYTES + g_off, pBh + kb);
            if (BSPL) cpa16(base + OF_BL * ARR_BYTES + g_off, pBl + kb);
            asm volatile("cp.async.commit_group;" ::: "memory");
            asm volatile("cp.async.wait_group 2;" ::: "memory");
        } else if (it + 1 < niter) {
            asm volatile("cp.async.wait_group 1;" ::: "memory");
        } else {
            asm volatile("cp.async.wait_group 0;" ::: "memory");
        }
        __syncthreads();

        const uint32_t sbase = sb + st * STG_BYTES;
        const uint32_t a_h = sbase + a_off;
        const uint32_t a_l = sbase + OF_AL * ARR_BYTES + a_off;
        const uint32_t b_h = sbase + OF_BH * ARR_BYTES + b_off;
        const uint32_t b_l = sbase + OF_BL * ARR_BYTES + b_off;

#pragma unroll
        for (int s = 0; s < 2; s++) {
            const uint32_t so = s * 16 * 2;
            uint32_t ah[2][4], al[2][4], bh[4][2], bl[4][2];
#pragma unroll
            for (int mt = 0; mt < 2; mt++) {
                LDSM4(ah[mt], a_h + so + mt * 16 * SAK * 2);
                if (ASPL) LDSM4(al[mt], a_l + so + mt * 16 * SAK * 2);
            }
#pragma unroll
            for (int p = 0; p < 2; p++) {
                uint32_t r4[4];
                LDSM4(r4, b_h + so + p * 16 * SAK * 2);
                bh[p * 2][0] = r4[0]; bh[p * 2][1] = r4[1];
                bh[p * 2 + 1][0] = r4[2]; bh[p * 2 + 1][1] = r4[3];
                if (BSPL) {
                    LDSM4(r4, b_l + so + p * 16 * SAK * 2);
                    bl[p * 2][0] = r4[0]; bl[p * 2][1] = r4[1];
                    bl[p * 2 + 1][0] = r4[2]; bl[p * 2 + 1][1] = r4[3];
                }
            }
#pragma unroll
            for (int mt = 0; mt < 2; mt++)
#pragma unroll
                for (int nt = 0; nt < 4; nt++) {
                    MMA_F32(acc[mt][nt], ah[mt], bh[nt]);
                    if (ASPL) MMA_F32(acc[mt][nt], al[mt], bh[nt]);
                    if (BSPL) MMA_F32(acc[mt][nt], ah[mt], bl[nt]);
                }
        }
        __syncthreads();
        st = (st == 2) ? 0 : st + 1;
        pfst = (pfst == 2) ? 0 : pfst + 1;
    }

    // epilogue
    const size_t Mtot = (size_t)gridDim.y * 128;
    float* Cb = C + (gridDim.z > 1 ? (size_t)blockIdx.z * Mtot * N : 0);
    const int er = (lane >> 2);
    const int ec = (lane & 3) * 2;
#pragma unroll
    for (int mt = 0; mt < 2; mt++) {
#pragma unroll
        for (int nt = 0; nt < 4; nt++) {
            int n = n0 + wn * 32 + nt * 8 + ec;
            float b0 = 0.f, b1 = 0.f;
            if (MODE == 0 && bias) { b0 = bias[n]; b1 = bias[n + 1]; }
#pragma unroll
            for (int h = 0; h < 2; h++) {
                int m = m0 + wm * 32 + mt * 16 + er + h * 8;
                float v0 = acc[mt][nt][h * 2 + 0] + b0;
                float v1 = acc[mt][nt][h * 2 + 1] + b1;
                if (MODE == 0) {
                    *(float2*)&Cb[(size_t)m * N + n] = make_float2(v0, v1);
                } else {
                    int b = m & 127, t = m >> 7;
                    float* o = &Cb[((size_t)b * TS + t) * VOCAB + n];
                    if (n < VOCAB) o[0] = v0;
                    if (n + 1 < VOCAB) o[1] = v1;
                }
            }
        }
    }
}

// ---------------------------------------------------------------------------
// fp32 SGEMM (small: ih/ic init, per-step wh) — f32x2
// ---------------------------------------------------------------------------
__device__ __forceinline__ void fma2(unsigned long long& d, unsigned long long a,
                                     unsigned long long b) {
    asm("fma.rn.f32x2 %0, %1, %2, %0;" : "+l"(d) : "l"(a), "l"(b));
}
__device__ __forceinline__ unsigned long long splat2(float x) {
    unsigned long long r;
    unsigned u = __float_as_uint(x);
    asm("mov.b64 %0, {%1, %1};" : "=l"(r) : "r"(u));
    return r;
}

template <int MODE>
__global__ void __launch_bounds__(128)
gemm_tile(const float* __restrict__ A, int lda,
          const float* __restrict__ W, int ldw,
          float* __restrict__ C, int N, int K,
          const float* __restrict__ bias)
{
    __shared__ float As[32][132];
    __shared__ float Ws[32][36];
    const int tid = threadIdx.x;
    const int n0 = blockIdx.x * 32, m0 = blockIdx.y * 128;
    const int kchunk = K / gridDim.z;
    const int kbeg = blockIdx.z * kchunk;
    const float* Ab = A + (size_t)m0 * lda;
    const int a_c = tid & 7, a_r = tid >> 3;
    const int ty = tid >> 3, tx = tid & 7;

    unsigned long long acc[4][4];
#pragma unroll
    for (int i = 0; i < 4; i++)
#pragma unroll
        for (int j = 0; j < 4; j++) acc[i][j] = 0ull;

    for (int kb = kbeg; kb < kbeg + kchunk; kb += 32) {
#pragma unroll
        for (int i = 0; i < 8; i++) {
            int r = a_r + 16 * i;
            float4 v = *reinterpret_cast<const float4*>(Ab + (size_t)r * lda + kb + 4 * a_c);
            As[4 * a_c + 0][r] = v.x; As[4 * a_c + 1][r] = v.y;
            As[4 * a_c + 2][r] = v.z; As[4 * a_c + 3][r] = v.w;
        }
#pragma unroll
        for (int i = 0; i < 2; i++) {
            int idx = tid + 128 * i;
            int r = idx >> 3, c = idx & 7;
            int n = n0 + r;
            float4 v = make_float4(0.f, 0.f, 0.f, 0.f);
            if (n < N) v = *reinterpret_cast<const float4*>(W + (size_t)n * ldw + kb + 4 * c);
            Ws[4 * c + 0][r] = v.x; Ws[4 * c + 1][r] = v.y;
            Ws[4 * c + 2][r] = v.z; Ws[4 * c + 3][r] = v.w;
        }
        __syncthreads();
#pragma unroll
        for (int kk = 0; kk < 32; kk++) {
            double2 a01 = *reinterpret_cast<const double2*>(&As[kk][ty * 8]);
            double2 a23 = *reinterpret_cast<const double2*>(&As[kk][ty * 8 + 4]);
            unsigned long long av[4] = {__double_as_longlong(a01.x), __double_as_longlong(a01.y),
                                        __double_as_longlong(a23.x), __double_as_longlong(a23.y)};
            float4 w = *reinterpret_cast<const float4*>(&Ws[kk][tx * 4]);
            unsigned long long wv[4] = {splat2(w.x), splat2(w.y), splat2(w.z), splat2(w.w)};
#pragma unroll
            for (int i = 0; i < 4; i++)
#pragma unroll
                for (int j = 0; j < 4; j++) fma2(acc[i][j], av[i], wv[j]);
        }
        __syncthreads();
    }

    const size_t Mtot = (size_t)gridDim.y * 128;
    float* Cb = C + (gridDim.z > 1 ? (size_t)blockIdx.z * Mtot * N : 0);
#pragma unroll
    for (int i = 0; i < 4; i++) {
        int mA = m0 + ty * 8 + 2 * i;
#pragma unroll
        for (int j = 0; j < 4; j++) {
            int n = n0 + tx * 4 + j;
            if (n >= N) continue;
            float2 p = *reinterpret_cast<float2*>(&acc[i][j]);
            float v0 = p.x, v1 = p.y;
            if (MODE == 1) { v0 = tanhf(v0 + bias[n]); v1 = tanhf(v1 + bias[n]); }
            else if (bias) { v0 += bias[n]; v1 += bias[n]; }
            Cb[(size_t)mA * N + n] = v0;
            Cb[(size_t)(mA + 1) * N + n] = v1;
        }
    }
}

// ---------------------------------------------------------------------------
// Prep / conversion kernels
// ---------------------------------------------------------------------------
#define NB_WX   8192
#define NB_V    12544
#define NB_EMBX 4864
#define NB_VPW  2048
#define NB_MEGA (NB_WX + NB_V + NB_EMBX + NB_VPW)

__global__ void mega_cvt4(const float* __restrict__ l1_Wih,
                          const float* __restrict__ V,
                          const float* __restrict__ embW,
                          const int* __restrict__ y,
                          const float* __restrict__ Vp_W,
                          __half* __restrict__ WXh, __half* __restrict__ WXl,
                          __half* __restrict__ Vh,  __half* __restrict__ Vl,
                          __half* __restrict__ EXh, __half* __restrict__ EXl,
                          __half* __restrict__ VWh, __half* __restrict__ VWl)
{
    int bid = blockIdx.x;
    if (bid < NB_WX) {
        int idx = bid * 256 + threadIdx.x;
        int r = idx >> 9, c = idx & 511;
        wr_hl16u(WXh, WXl, idx, l1_Wih[(size_t)r * 1536 + c]);
    } else if (bid < NB_WX + NB_V) {
        int idx = (bid - NB_WX) * 256 + threadIdx.x;
        wr_hl16u(Vh, Vl, idx, V[idx]);
    } else if (bid < NB_WX + NB_V + NB_EMBX) {
        int idx = (bid - NB_WX - NB_V) * 256 + threadIdx.x;
        int e = idx & 511;
        int b = (idx >> 9) & 127;
        int t = idx >> 16;
        wr_hl16u(EXh, EXl, idx, embW[(size_t)y[b * TT + t] * EMB + e]);
    } else {
        int idx = (bid - NB_WX - NB_V - NB_EMBX) * 256 + threadIdx.x;
        wr_hl16u(VWh, VWl, idx, Vp_W[idx]);
    }
}

__global__ void cvt_hl(const float* __restrict__ src, int ld, int rows, int cols,
                       __half* __restrict__ hi, __half* __restrict__ lo, int rowsPad)
{
    int idx = blockIdx.x * 256 + threadIdx.x;
    if (idx >= rowsPad * cols) return;
    int r = idx / cols, c = idx - r * cols;
    float x = (r < rows) ? src[(size_t)r * ld + c] : 0.f;
    wr_hl16u(hi, lo, idx, x);
}

__global__ void cvt_h(const float* __restrict__ src, int ld, int rows, int cols,
                      __half* __restrict__ dst, int rowsPad)
{
    int idx = blockIdx.x * 256 + threadIdx.x;
    if (idx >= rowsPad * cols) return;
    int r = idx / cols, c = idx - r * cols;
    float x = (r < rows) ? src[(size_t)r * ld + c] : 0.f;
    dst[idx] = __float2half(x);
}

__global__ void build_wcat_hl(__half* __restrict__ hi, __half* __restrict__ lo,
                              const float* __restrict__ Wih, int ld_ih, int coff,
                              const float* __restrict__ Whh)
{
    int idx = blockIdx.x * 256 + threadIdx.x;
    if (idx >= G4 * 2048) return;
    int n = idx >> 11, k = idx & 2047;
    float x = (k < 1024) ? Wih[(size_t)n * ld_ih + coff + k]
                         : Whh[(size_t)n * 1024 + (k - 1024)];
    wr_hl16u(hi, lo, idx, x);
}

__global__ void add_bias_kernel(float* __restrict__ dst, const float* __restrict__ a,
                                const float* __restrict__ b, int n)
{
    int i = blockIdx.x * 256 + threadIdx.x;
    if (i < n) dst[i] = a[i] + b[i];
}

__global__ void feat_mean_kernel(const float* __restrict__ Vp, float* __restrict__ fm)
{
    int idx = blockIdx.x * 256 + threadIdx.x;
    if (idx >= BB * HD) return;
    int b = idx >> 10, h = idx & 1023;
    const float* p = Vp + (size_t)b * NN * HD + h;
    float s = 0.f;
#pragma unroll 7
    for (int n = 0; n < NN; n++) s += p[n * HD];
    fm[idx] = s * (1.f / 49.f);
}

// ---------------------------------------------------------------------------
// Attention: sums WHZ wh partials, warp softmax, ctx; X1=[ctx|h1] hi/lo
// ---------------------------------------------------------------------------
__global__ void attn_kernel(const float* __restrict__ Vp, const float* __restrict__ Uv,
                            const float* __restrict__ whp, const float* __restrict__ attv,
                            const float* __restrict__ h1cur,
                            __half* __restrict__ x1h, __half* __restrict__ x1l)
{
    int b = blockIdx.x, tid = threadIdx.x;
    __shared__ float s_wh[ATT];
    __shared__ float s_e[NN];

    for (int a = tid; a < ATT; a += 256) {
        int o = b * ATT + a;
        float s = 0.f;
#pragma unroll
        for (int z = 0; z < WHZ; z++) s += whp[z * BB * ATT + o];
        s_wh[a] = s;
    }
    __syncthreads();

    int warp = tid >> 5, lane = tid & 31;
    for (int n = warp; n < NN; n += 8) {
        const float* uv = Uv + ((size_t)b * NN + n) * ATT;
        float s = 0.f;
        for (int a = lane; a < ATT; a += 32) s += tanhf(s_wh[a] + uv[a]) * attv[a];
#pragma unroll
        for (int o = 16; o > 0; o >>= 1) s += __shfl_down_sync(0xffffffffu, s, o);
        if (lane == 0) s_e[n] = s;
    }
    __syncthreads();

    if (warp == 0) {
        float m = -1e30f;
        for (int n = lane; n < NN; n += 32) m = fmaxf(m, s_e[n]);
#pragma unroll
        for (int o = 16; o > 0; o >>= 1) m = fmaxf(m, __shfl_xor_sync(0xffffffffu, m, o));
        float S = 0.f;
        float v0 = 0.f, v1 = 0.f;
        if (lane < NN) { v0 = expf(s_e[lane] - m); S += v0; }
        if (lane + 32 < NN) { v1 = expf(s_e[lane + 32] - m); S += v1; }
#pragma unroll
        for (int o = 16; o > 0; o >>= 1) S += __shfl_xor_sync(0xffffffffu, S, o);
        float inv = 1.f / S;
        if (lane < NN) s_e[lane] = v0 * inv;
        if (lane + 32 < NN) s_e[lane + 32] = v1 * inv;
    }
    __syncthreads();

    const float* vpb = Vp + (size_t)b * NN * HD;
    for (int h = tid; h < HD; h += 256) {
        float acc = 0.f;
#pragma unroll 7
        for (int n = 0; n < NN; n++) acc += s_e[n] * vpb[n * HD + h];
        wr_hl16u(x1h, x1l, (size_t)b * 2048 + h, acc);
    }
    for (int h = tid; h < HD; h += 256)
        wr_hl16u(x1h, x1l, (size_t)b * 2048 + 1024 + h, h1cur[b * HD + h]);
}

// ---------------------------------------------------------------------------
// LSTM cell + LN fused with splitK (ZK) gate reduction — 512 threads
// ---------------------------------------------------------------------------
__global__ void __launch_bounds__(512)
lstm_ln_kernel(const float* __restrict__ gp, const float* __restrict__ bias,
               const float* __restrict__ extra,
               const float* __restrict__ cin, float* __restrict__ cout,
               const float* __restrict__ gam, const float* __restrict__ bet,
               float* __restrict__ hout,
               __half* __restrict__ x2h, __half* __restrict__ x2l,
               const float* __restrict__ h2cur)
{
    const size_t BG = (size_t)BB * G4;
    int b = blockIdx.x, tid = threadIdx.x;
    __shared__ float s_h[HD];
    __shared__ float s_red[64];
    __shared__ float s_mu, s_rstd;

    float sum = 0.f, sq = 0.f;
    for (int h = tid; h < HD; h += 512) {
        float g[4];
#pragma unroll
        for (int q = 0; q < 4; q++) {
            size_t idx = (size_t)b * G4 + q * 1024 + h;
            float v = bias[q * 1024 + h];
#pragma unroll
            for (int z = 0; z < ZK; z++) v += gp[z * BG + idx];
            if (extra) v += extra[idx];
            g[q] = v;
        }
        float c = sigf(g[1]) * cin[b * HD + h] + sigf(g[0]) * tanhf(g[2]);
        cout[b * HD + h] = c;
        float hv = sigf(g[3]) * tanhf(c);
        s_h[h] = hv;
        sum += hv; sq += hv * hv;
    }
#pragma unroll
    for (int o = 16; o > 0; o >>= 1) {
        sum += __shfl_down_sync(0xffffffffu, sum, o);
        sq  += __shfl_down_sync(0xffffffffu, sq,  o);
    }
    int warp = tid >> 5, lane = tid & 31;
    if (lane == 0) { s_red[warp] = sum; s_red[32 + warp] = sq; }
    __syncthreads();
    if (tid == 0) {
        float S = 0.f, Q = 0.f;
        for (int w = 0; w < 16; w++) { S += s_red[w]; Q += s_red[32 + w]; }
        float mu = S * (1.f / 1024.f);
        float var = Q * (1.f / 1024.f) - mu * mu;
        s_mu = mu; s_rstd = 1.f / sqrtf(var + 1e-5f);
    }
    __syncthreads();
    float mu = s_mu, rstd = s_rstd;
    for (int h = tid; h < HD; h += 512) {
        float v = (s_h[h] - mu) * rstd * gam[h] + bet[h];
        hout[b * HD + h] = v;
        if (x2h) wr_hl16u(x2h, x2l, (size_t)b * 2048 + h, v);
    }
    if (x2h)
        for (int h = tid; h < HD; h += 512)
            wr_hl16u(x2h, x2l, (size_t)b * 2048 + 1024 + h, h2cur[b * HD + h]);
}

// ---------------------------------------------------------------------------
// Launch
// ---------------------------------------------------------------------------
extern "C" void kernel_launch(void* const* d_in, const int* in_sizes, int n_in,
                              void* d_out, int out_size)
{
    (void)in_sizes; (void)n_in; (void)out_size;
    const float* V      = (const float*)d_in[0];
    const int*   y      = (const int*)  d_in[1];
    const float* embW   = (const float*)d_in[2];
    const float* Vp_W   = (const float*)d_in[3];
    const float* Vp_b   = (const float*)d_in[4];
    const float* attW   = (const float*)d_in[5];
    const float* attU   = (const float*)d_in[6];
    const float* attv   = (const float*)d_in[7];
    const float* l1_Wih = (const float*)d_in[8];
    const float* l1_Whh = (const float*)d_in[9];
    const float* l1_bih = (const float*)d_in[10];
    const float* l1_bhh = (const float*)d_in[11];
    const float* l2_Wih = (const float*)d_in[12];
    const float* l2_Whh = (const float*)d_in[13];
    const float* l2_bih = (const float*)d_in[14];
    const float* l2_bhh = (const float*)d_in[15];
    const float* n1_g   = (const float*)d_in[16];
    const float* n1_b   = (const float*)d_in[17];
    const float* n2_g   = (const float*)d_in[18];
    const float* n2_b   = (const float*)d_in[19];
    const float* ih_W   = (const float*)d_in[20];
    const float* ih_b   = (const float*)d_in[21];
    const float* ic_W   = (const float*)d_in[22];
    const float* ic_b   = (const float*)d_in[23];
    const float* proj_W = (const float*)d_in[24];
    float* out = (float*)d_out;

    cudaFuncSetAttribute(hmma_gemm<0, 1, 1>, cudaFuncAttributeMaxDynamicSharedMemorySize, HM_SMEM4);
    cudaFuncSetAttribute(hmma_gemm<0, 0, 0>, cudaFuncAttributeMaxDynamicSharedMemorySize, HM_SMEM2);
    cudaFuncSetAttribute(hmma_gemm<3, 0, 0>, cudaFuncAttributeMaxDynamicSharedMemorySize, HM_SMEM2);

    float* buf = nullptr;
    cudaGetSymbolAddress((void**)&buf, g_buf);
    __half* hf = nullptr;
    cudaGetSymbolAddress((void**)&hf, g_hf);

    float* VP  = buf + OFF_VP;
    float* UV  = buf + OFF_UV;
    float* FM  = buf + OFF_FM;
    float* H1  = buf + OFF_H1;
    float* C1  = buf + OFF_C1;
    float* C2  = buf + OFF_C2;
    float* H2A = buf + OFF_H2A;
    float* G1X = buf + OFF_G1X;
    float* B1  = buf + OFF_B1;
    float* B2  = buf + OFF_B2;
    float* GP  = buf + OFF_GP;
    float* WHP = buf + OFF_WHP;
    float* PF  = buf + OFF_PF;

    __half *W1h = hf + HO_W1,   *W1l = W1h + SZ_W1;      // hi/lo (3-pass)
    __half *W2h = hf + HO_W2,   *W2l = W2h + SZ_W2;      // hi/lo (3-pass)
    __half *EWs = hf + HO_EMBW;                          // single (1-pass logits)
    __half *PJh = hf + HO_PROJ, *PJl = PJh + SZ_PROJ;    // hi/lo (3-pass)
    __half *AUs = hf + HO_ATTU;                          // single (1-pass Uv)
    __half *VWh = hf + HO_VPW,  *VWl = VWh + SZ_VPW;     // hi/lo (3-pass)
    __half *WXh = hf + HO_WX,   *WXl = WXh + SZ_WX;      // hi/lo (3-pass)
    __half *Vh  = hf + HO_V,    *Vl  = Vh  + SZ_V;
    __half *VPs = hf + HO_VPB;                           // single (1-pass Uv)
    __half *EXh = hf + HO_EMBX, *EXl = EXh + SZ_EMBX;
    __half *X1h = hf + HO_X1,   *X1l = X1h + SZ_X1;
    __half *X2h = hf + HO_X2,   *X2l = X2h + SZ_X2;
    __half *H2h = hf + HO_H2,   *H2l = H2h + SZ_H2;
    __half *Ps  = hf + HO_P;                             // single (1-pass logits)

    const int SLOT = BB * HD;
    auto nb = [](size_t tot) { return (unsigned)((tot + 255) / 256); };

    // ---- launch #1: fused conversion of critical-path operands ----
    mega_cvt4<<<NB_MEGA, 256>>>(l1_Wih, V, embW, y, Vp_W,
                                WXh, WXl, Vh, Vl, EXh, EXl, VWh, VWl);
    // launches #2..#4: hmma GEMMs (ncu capture window)
    hmma_gemm<0, 1, 1><<<dim3(G4 / 128, 10, 1), 512, HM_SMEM4>>>(EXh, EXl, EMB, WXh, WXl, EMB,
                                                                 G1X, G4, EMB, nullptr);
    hmma_gemm<0, 1, 1><<<dim3(G4 / 128, 9, 1), 512, HM_SMEM4>>>(EXh + (size_t)1280 * EMB,
                                                                EXl + (size_t)1280 * EMB, EMB,
                                                                WXh, WXl, EMB,
                                                                G1X + (size_t)1280 * G4, G4, EMB,
                                                                nullptr);
    hmma_gemm<0, 1, 1><<<dim3(HD / 128, NN, 1), 512, HM_SMEM4>>>(Vh, Vl, VD, VWh, VWl, VD,
                                                                 VP, HD, VD, Vp_b);

    build_wcat_hl<<<nb((size_t)G4 * 2048), 256>>>(W1h, W1l, l1_Wih, 1536, 512, l1_Whh);
    build_wcat_hl<<<nb((size_t)G4 * 2048), 256>>>(W2h, W2l, l2_Wih, 1024, 0, l2_Whh);
    cvt_h<<<nb((size_t)NVP * EMB), 256>>>(embW, EMB, VOCAB, EMB, EWs, NVP);
    cvt_hl<<<nb(SZ_PROJ), 256>>>(proj_W, HD, EMB, HD, PJh, PJl, EMB);
    cvt_h<<<nb(SZ_ATTU), 256>>>(attU, HD, ATT, HD, AUs, ATT);
    add_bias_kernel<<<32, 256>>>(B1, l1_bih, l1_bhh, G4);
    add_bias_kernel<<<32, 256>>>(B2, l2_bih, l2_bhh, G4);

    cvt_h<<<nb(SZ_VPB), 256>>>(VP, HD, BB * NN, HD, VPs, BB * NN);
    feat_mean_kernel<<<nb((size_t)BB * HD), 256>>>(VP, FM);
    gemm_tile<1><<<dim3(HD / 32, 1, 1), 128>>>(FM, HD, ih_W, HD, H1, HD, HD, ih_b);
    gemm_tile<1><<<dim3(HD / 32, 1, 1), 128>>>(FM, HD, ic_W, HD, C1, HD, HD, ic_b);
    // Uv (1-pass; softmax-damped): Vp @ attU^T
    hmma_gemm<0, 0, 0><<<dim3(ATT / 128, NN, 1), 512, HM_SMEM2>>>(VPs, nullptr, HD, AUs, nullptr,
                                                                  HD, UV, ATT, HD, nullptr);

    cudaMemsetAsync(H2A, 0, (size_t)SLOT * sizeof(float), 0);
    cudaMemsetAsync(C2, 0, (size_t)SLOT * sizeof(float), 0);

    // ---- sequential decode ----
    for (int t = 0; t < TS; t++) {
        const float* h2c = H2A + (size_t)t * SLOT;
        gemm_tile<0><<<dim3(ATT / 32, 1, WHZ), 128>>>(h2c, HD, attW, HD, WHP, ATT, HD, nullptr);
        attn_kernel<<<BB, 256>>>(VP, UV, WHP, attv, H1 + (size_t)(t & 1) * SLOT, X1h, X1l);
        hmma_gemm<0, 1, 1><<<dim3(G4 / 128, 1, ZK), 512, HM_SMEM4>>>(X1h, X1l, 2048, W1h, W1l,
                                                                     2048, GP, G4, 2048, nullptr);
        lstm_ln_kernel<<<BB, 512>>>(GP, B1, G1X + (size_t)t * BB * G4,
                                    C1 + (size_t)(t & 1) * SLOT,
                                    C1 + (size_t)((t + 1) & 1) * SLOT,
                                    n1_g, n1_b, H1 + (size_t)((t + 1) & 1) * SLOT,
                                    X2h, X2l, h2c);
        hmma_gemm<0, 1, 1><<<dim3(G4 / 128, 1, ZK), 512, HM_SMEM4>>>(X2h, X2l, 2048, W2h, W2l,
                                                                     2048, GP, G4, 2048, nullptr);
        lstm_ln_kernel<<<BB, 512>>>(GP, B2, nullptr,
                                    C2 + (size_t)(t & 1) * SLOT,
                                    C2 + (size_t)((t + 1) & 1) * SLOT,
                                    n2_g, n2_b, H2A + (size_t)(t + 1) * SLOT,
                                    nullptr, nullptr, nullptr);
    }

    // ---- deferred output projection (proj 3-pass, logits 1-pass) ----
    cvt_hl<<<nb(SZ_H2), 256>>>(H2A + SLOT, HD, TS * BB, HD, H2h, H2l, TS * BB);
    hmma_gemm<0, 1, 1><<<dim3(EMB / 128, TS, 1), 512, HM_SMEM4>>>(H2h, H2l, HD, PJh, PJl, HD,
                                                                  PF, EMB, HD, nullptr);
    cvt_h<<<nb(SZ_P), 256>>>(PF, EMB, TS * BB, EMB, Ps, TS * BB);
    hmma_gemm<3, 0, 0><<<dim3(NVP / 128, TS, 1), 512, HM_SMEM2>>>(Ps, nullptr, EMB, EWs, nullptr,
                                                                  EMB, out, VOCAB, EMB, nullptr);
}

// round 17
// speedup vs baseline: 1.1996x; 1.0207x over previous
#include <cuda_runtime.h>
#include <cuda_fp16.h>
#include <cstdint>

// ---------------------------------------------------------------------------
// Problem constants
// ---------------------------------------------------------------------------
#define BB   128
#define TT   20
#define TS   19
#define NN   49
#define VOCAB 10000
#define NVP  10112       // VOCAB padded to 79*128
#define EMB  512
#define HD   1024
#define VD   512
#define ATT  512
#define G4   4096
#define ZK   4           // split-K for sequential gates GEMMs
#define WHZ  8           // split-K for wh GEMM

// ---------------------------------------------------------------------------
// fp32 scratch
// ---------------------------------------------------------------------------
#define OFF_VP    ((size_t)0)
#define OFF_UV    (OFF_VP   + (size_t)BB*NN*HD)
#define OFF_FM    (OFF_UV   + (size_t)BB*NN*ATT)
#define OFF_H1    (OFF_FM   + (size_t)BB*HD)
#define OFF_C1    (OFF_H1   + (size_t)2*BB*HD)
#define OFF_C2    (OFF_C1   + (size_t)2*BB*HD)
#define OFF_H2A   (OFF_C2   + (size_t)2*BB*HD)
#define OFF_G1X   (OFF_H2A  + (size_t)TT*BB*HD)
#define OFF_B1    (OFF_G1X  + (size_t)TS*BB*G4)
#define OFF_B2    (OFF_B1   + (size_t)G4)
#define OFF_GP    (OFF_B2   + (size_t)G4)                  // [ZK,B,4096]
#define OFF_WHP   (OFF_GP   + (size_t)ZK*BB*G4)            // [WHZ,B,ATT]
#define OFF_PF    (OFF_WHP  + (size_t)WHZ*BB*ATT)
#define BUF_TOTAL (OFF_PF   + (size_t)TS*BB*EMB)
__device__ float g_buf[BUF_TOTAL];

// ---------------------------------------------------------------------------
// fp16 scratch
// ---------------------------------------------------------------------------
#define SZ_W1   ((size_t)G4*2048)
#define SZ_W2   ((size_t)G4*2048)
#define SZ_EMBW ((size_t)NVP*EMB)
#define SZ_PROJ ((size_t)EMB*HD)
#define SZ_ATTU ((size_t)ATT*HD)
#define SZ_VPW  ((size_t)HD*VD)
#define SZ_WX   ((size_t)G4*EMB)
#define SZ_V    ((size_t)BB*NN*VD)
#define SZ_VPB  ((size_t)BB*NN*HD)
#define SZ_EMBX ((size_t)TS*BB*EMB)
#define SZ_X1   ((size_t)BB*2048)
#define SZ_X2   ((size_t)BB*2048)
#define SZ_H2   ((size_t)TS*BB*HD)
#define SZ_P    ((size_t)TS*BB*EMB)

#define HO_W1   ((size_t)0)
#define HO_W2   (HO_W1   + 2*SZ_W1)
#define HO_EMBW (HO_W2   + 2*SZ_W2)
#define HO_PROJ (HO_EMBW + SZ_EMBW)
#define HO_ATTU (HO_PROJ + 2*SZ_PROJ)
#define HO_VPW  (HO_ATTU + SZ_ATTU)
#define HO_WX   (HO_VPW  + 2*SZ_VPW)
#define HO_V    (HO_WX   + 2*SZ_WX)
#define HO_VPB  (HO_V    + 2*SZ_V)
#define HO_EMBX (HO_VPB  + SZ_VPB)
#define HO_X1   (HO_EMBX + 2*SZ_EMBX)
#define HO_X2   (HO_X1   + 2*SZ_X1)
#define HO_H2   (HO_X2   + 2*SZ_X2)
#define HO_P    (HO_H2   + 2*SZ_H2)
#define HF_TOTAL (HO_P   + SZ_P)
__device__ __half g_hf[HF_TOTAL];

__device__ __forceinline__ float sigf(float x) { return 1.f / (1.f + expf(-x)); }

// unscaled fp16 hi/lo split: x ~= hi + lo  (captures ~22 mantissa bits)
__device__ __forceinline__ void wr_hl16u(__half* hi, __half* lo, size_t idx, float x) {
    __half h = __float2half(x);
    hi[idx] = h;
    lo[idx] = __float2half(x - __half2float(h));
}

__device__ __forceinline__ uint32_t smem_u32(const void* p) {
    uint32_t a;
    asm("{ .reg .u64 t; cvta.to.shared.u64 t, %1; cvt.u32.u64 %0, t; }" : "=r"(a) : "l"(p));
    return a;
}

// ---------------------------------------------------------------------------
// HMMA primitives (base PTX, sm_80+)
// ---------------------------------------------------------------------------
#define LDSM4(r, a) \
    asm volatile("ldmatrix.sync.aligned.m8n8.x4.shared.b16 {%0,%1,%2,%3}, [%4];" \
        : "=r"((r)[0]), "=r"((r)[1]), "=r"((r)[2]), "=r"((r)[3]) : "r"(a))

#define MMA_F32(d, a, b) \
    asm volatile("mma.sync.aligned.m16n8k16.row.col.f32.f16.f16.f32 " \
        "{%0,%1,%2,%3}, {%4,%5,%6,%7}, {%8,%9}, {%0,%1,%2,%3};" \
        : "+f"((d)[0]), "+f"((d)[1]), "+f"((d)[2]), "+f"((d)[3]) \
        : "r"((a)[0]), "r"((a)[1]), "r"((a)[2]), "r"((a)[3]), \
          "r"((b)[0]), "r"((b)[1]))

__device__ __forceinline__ void cpa16(uint32_t dst, const void* src) {
    asm volatile("cp.async.cg.shared.global [%0], [%1], 16;" :: "r"(dst), "l"(src));
}

// ---------------------------------------------------------------------------
// Pipelined HMMA GEMM: C[M,N] = A[M,K] @ B[N,K]^T, fp16 unscaled hi/lo.
// ASPL: A split (adds Al*Bh pass). BSPL: B split (adds Ah*Bl pass).
// BM=128, BN=128, BK=64 (half the barrier count vs BK=32), 512 threads
// (4x4 warps, warp tile 32x32). 2-stage cp.async double buffer.
// MODE 0: fp32 store (+bias), splitK z partials.  MODE 3: logits permuted store.
// ---------------------------------------------------------------------------
#define SAK 72                              // 64 + 8 pad (144B rows, ldsm conflict-free)
#define ARR_BYTES (128 * SAK * 2)           // 18432
#define HM_SMEM4  (2 * 4 * ARR_BYTES)       // 147456 (3-pass, 2 stages)
#define HM_SMEM2  (2 * 2 * ARR_BYTES)       // 73728  (1-pass, 2 stages)

template <int MODE, int BSPL, int ASPL>
__global__ void __launch_bounds__(512, 1)
hmma_gemm(const __half* __restrict__ Ahi, const __half* __restrict__ Alo, int lda,
          const __half* __restrict__ Bhi, const __half* __restrict__ Blo, int ldb,
          float* __restrict__ C, int N, int K,
          const float* __restrict__ bias)
{
    constexpr uint32_t NARR = 2 + ASPL + BSPL;
    constexpr uint32_t STG_BYTES = NARR * ARR_BYTES;
    constexpr uint32_t OF_AL = 1;
    constexpr uint32_t OF_BH = 1 + ASPL;
    constexpr uint32_t OF_BL = 2 + ASPL;

    extern __shared__ __half smh[];
    uint32_t sb = smem_u32(smh);

    const int tid  = threadIdx.x;
    const int lane = tid & 31, wid = tid >> 5;
    const int wm = wid & 3;
    const int wn = wid >> 2;
    const int n0 = blockIdx.x * 128, m0 = blockIdx.y * 128;
    const int kchunk = K / gridDim.z;
    const int kbeg   = blockIdx.z * kchunk;
    const int niter  = kchunk >> 6;          // BK = 64

    const int lr = tid >> 2;                 // 0..127
    const int lc = (tid & 3) * 8;            // 0/8/16/24 (elements)

    float acc[2][4][4];
#pragma unroll
    for (int i = 0; i < 2; i++)
#pragma unroll
        for (int j = 0; j < 4; j++)
#pragma unroll
            for (int q = 0; q < 4; q++) acc[i][j][q] = 0.f;

    const int arow = wm * 32 + (lane & 15);
    const int acol = (lane >> 4) * 8;
    const int brow = wn * 32 + ((lane >> 4) * 8) + (lane & 7);
    const int bcol = ((lane >> 3) & 1) * 8;
    const uint32_t a_off = (uint32_t)(arow * SAK + acol) * 2;
    const uint32_t b_off = (uint32_t)(brow * SAK + bcol) * 2;

    const uint32_t g_off = (uint32_t)(lr * SAK + lc) * 2;   // bytes; 2nd chunk +64B
    const __half* pAh = Ahi + (size_t)(m0 + lr) * lda + lc;
    const __half* pAl = ASPL ? (Alo + (size_t)(m0 + lr) * lda + lc) : nullptr;
    const __half* pBh = Bhi + (size_t)(n0 + lr) * ldb + lc;
    const __half* pBl = BSPL ? (Blo + (size_t)(n0 + lr) * ldb + lc) : nullptr;

    // prefetch stage 0
    {
        const int kb = kbeg;
        cpa16(sb + 0 * ARR_BYTES + g_off, pAh + kb);
        cpa16(sb + 0 * ARR_BYTES + g_off + 64, pAh + kb + 32);
        if (ASPL) {
            cpa16(sb + OF_AL * ARR_BYTES + g_off, pAl + kb);
            cpa16(sb + OF_AL * ARR_BYTES + g_off + 64, pAl + kb + 32);
        }
        cpa16(sb + OF_BH * ARR_BYTES + g_off, pBh + kb);
        cpa16(sb + OF_BH * ARR_BYTES + g_off + 64, pBh + kb + 32);
        if (BSPL) {
            cpa16(sb + OF_BL * ARR_BYTES + g_off, pBl + kb);
            cpa16(sb + OF_BL * ARR_BYTES + g_off + 64, pBl + kb + 32);
        }
        asm volatile("cp.async.commit_group;" ::: "memory");
    }

    for (int it = 0; it < niter; it++) {
        if (it + 1 < niter) {
            const int kb = kbeg + (it + 1) * 64;
            uint32_t base = sb + ((it + 1) & 1) * STG_BYTES;
            cpa16(base + 0 * ARR_BYTES + g_off, pAh + kb);
            cpa16(base + 0 * ARR_BYTES + g_off + 64, pAh + kb + 32);
            if (ASPL) {
                cpa16(base + OF_AL * ARR_BYTES + g_off, pAl + kb);
                cpa16(base + OF_AL * ARR_BYTES + g_off + 64, pAl + kb + 32);
            }
            cpa16(base + OF_BH * ARR_BYTES + g_off, pBh + kb);
            cpa16(base + OF_BH * ARR_BYTES + g_off + 64, pBh + kb + 32);
            if (BSPL) {
                cpa16(base + OF_BL * ARR_BYTES + g_off, pBl + kb);
                cpa16(base + OF_BL * ARR_BYTES + g_off + 64, pBl + kb + 32);
            }
            asm volatile("cp.async.commit_group;" ::: "memory");
            asm volatile("cp.async.wait_group 1;" ::: "memory");
        } else {
            asm volatile("cp.async.wait_group 0;" ::: "memory");
        }
        __syncthreads();

        const uint32_t sbase = sb + (it & 1) * STG_BYTES;
        const uint32_t a_h = sbase + a_off;
        const uint32_t a_l = sbase + OF_AL * ARR_BYTES + a_off;
        const uint32_t b_h = sbase + OF_BH * ARR_BYTES + b_off;
        const uint32_t b_l = sbase + OF_BL * ARR_BYTES + b_off;

#pragma unroll
        for (int s = 0; s < 4; s++) {
            const uint32_t so = s * 16 * 2;
            uint32_t ah[2][4], al[2][4], bh[4][2], bl[4][2];
#pragma unroll
            for (int mt = 0; mt < 2; mt++) {
                LDSM4(ah[mt], a_h + so + mt * 16 * SAK * 2);
                if (ASPL) LDSM4(al[mt], a_l + so + mt * 16 * SAK * 2);
            }
#pragma unroll
            for (int p = 0; p < 2; p++) {
                uint32_t r4[4];
                LDSM4(r4, b_h + so + p * 16 * SAK * 2);
                bh[p * 2][0] = r4[0]; bh[p * 2][1] = r4[1];
                bh[p * 2 + 1][0] = r4[2]; bh[p * 2 + 1][1] = r4[3];
                if (BSPL) {
                    LDSM4(r4, b_l + so + p * 16 * SAK * 2);
                    bl[p * 2][0] = r4[0]; bl[p * 2][1] = r4[1];
                    bl[p * 2 + 1][0] = r4[2]; bl[p * 2 + 1][1] = r4[3];
                }
            }
#pragma unroll
            for (int mt = 0; mt < 2; mt++)
#pragma unroll
                for (int nt = 0; nt < 4; nt++) {
                    MMA_F32(acc[mt][nt], ah[mt], bh[nt]);
                    if (ASPL) MMA_F32(acc[mt][nt], al[mt], bh[nt]);
                    if (BSPL) MMA_F32(acc[mt][nt], ah[mt], bl[nt]);
                }
        }
        __syncthreads();
    }

    // epilogue
    const size_t Mtot = (size_t)gridDim.y * 128;
    float* Cb = C + (gridDim.z > 1 ? (size_t)blockIdx.z * Mtot * N : 0);
    const int er = (lane >> 2);
    const int ec = (lane & 3) * 2;
#pragma unroll
    for (int mt = 0; mt < 2; mt++) {
#pragma unroll
        for (int nt = 0; nt < 4; nt++) {
            int n = n0 + wn * 32 + nt * 8 + ec;
            float b0 = 0.f, b1 = 0.f;
            if (MODE == 0 && bias) { b0 = bias[n]; b1 = bias[n + 1]; }
#pragma unroll
            for (int h = 0; h < 2; h++) {
                int m = m0 + wm * 32 + mt * 16 + er + h * 8;
                float v0 = acc[mt][nt][h * 2 + 0] + b0;
                float v1 = acc[mt][nt][h * 2 + 1] + b1;
                if (MODE == 0) {
                    *(float2*)&Cb[(size_t)m * N + n] = make_float2(v0, v1);
                } else {
                    int b = m & 127, t = m >> 7;
                    float* o = &Cb[((size_t)b * TS + t) * VOCAB + n];
                    if (n < VOCAB) o[0] = v0;
                    if (n + 1 < VOCAB) o[1] = v1;
                }
            }
        }
    }
}

// ---------------------------------------------------------------------------
// fp32 SGEMM (small: ih/ic init, per-step wh) — f32x2
// ---------------------------------------------------------------------------
__device__ __forceinline__ void fma2(unsigned long long& d, unsigned long long a,
                                     unsigned long long b) {
    asm("fma.rn.f32x2 %0, %1, %2, %0;" : "+l"(d) : "l"(a), "l"(b));
}
__device__ __forceinline__ unsigned long long splat2(float x) {
    unsigned long long r;
    unsigned u = __float_as_uint(x);
    asm("mov.b64 %0, {%1, %1};" : "=l"(r) : "r"(u));
    return r;
}

template <int MODE>
__global__ void __launch_bounds__(128)
gemm_tile(const float* __restrict__ A, int lda,
          const float* __restrict__ W, int ldw,
          float* __restrict__ C, int N, int K,
          const float* __restrict__ bias)
{
    __shared__ float As[32][132];
    __shared__ float Ws[32][36];
    const int tid = threadIdx.x;
    const int n0 = blockIdx.x * 32, m0 = blockIdx.y * 128;
    const int kchunk = K / gridDim.z;
    const int kbeg = blockIdx.z * kchunk;
    const float* Ab = A + (size_t)m0 * lda;
    const int a_c = tid & 7, a_r = tid >> 3;
    const int ty = tid >> 3, tx = tid & 7;

    unsigned long long acc[4][4];
#pragma unroll
    for (int i = 0; i < 4; i++)
#pragma unroll
        for (int j = 0; j < 4; j++) acc[i][j] = 0ull;

    for (int kb = kbeg; kb < kbeg + kchunk; kb += 32) {
#pragma unroll
        for (int i = 0; i < 8; i++) {
            int r = a_r + 16 * i;
            float4 v = *reinterpret_cast<const float4*>(Ab + (size_t)r * lda + kb + 4 * a_c);
            As[4 * a_c + 0][r] = v.x; As[4 * a_c + 1][r] = v.y;
            As[4 * a_c + 2][r] = v.z; As[4 * a_c + 3][r] = v.w;
        }
#pragma unroll
        for (int i = 0; i < 2; i++) {
            int idx = tid + 128 * i;
            int r = idx >> 3, c = idx & 7;
            int n = n0 + r;
            float4 v = make_float4(0.f, 0.f, 0.f, 0.f);
            if (n < N) v = *reinterpret_cast<const float4*>(W + (size_t)n * ldw + kb + 4 * c);
            Ws[4 * c + 0][r] = v.x; Ws[4 * c + 1][r] = v.y;
            Ws[4 * c + 2][r] = v.z; Ws[4 * c + 3][r] = v.w;
        }
        __syncthreads();
#pragma unroll
        for (int kk = 0; kk < 32; kk++) {
            double2 a01 = *reinterpret_cast<const double2*>(&As[kk][ty * 8]);
            double2 a23 = *reinterpret_cast<const double2*>(&As[kk][ty * 8 + 4]);
            unsigned long long av[4] = {__double_as_longlong(a01.x), __double_as_longlong(a01.y),
                                        __double_as_longlong(a23.x), __double_as_longlong(a23.y)};
            float4 w = *reinterpret_cast<const float4*>(&Ws[kk][tx * 4]);
            unsigned long long wv[4] = {splat2(w.x), splat2(w.y), splat2(w.z), splat2(w.w)};
#pragma unroll
            for (int i = 0; i < 4; i++)
#pragma unroll
                for (int j = 0; j < 4; j++) fma2(acc[i][j], av[i], wv[j]);
        }
        __syncthreads();
    }

    const size_t Mtot = (size_t)gridDim.y * 128;
    float* Cb = C + (gridDim.z > 1 ? (size_t)blockIdx.z * Mtot * N : 0);
#pragma unroll
    for (int i = 0; i < 4; i++) {
        int mA = m0 + ty * 8 + 2 * i;
#pragma unroll
        for (int j = 0; j < 4; j++) {
            int n = n0 + tx * 4 + j;
            if (n >= N) continue;
            float2 p = *reinterpret_cast<float2*>(&acc[i][j]);
            float v0 = p.x, v1 = p.y;
            if (MODE == 1) { v0 = tanhf(v0 + bias[n]); v1 = tanhf(v1 + bias[n]); }
            else if (bias) { v0 += bias[n]; v1 += bias[n]; }
            Cb[(size_t)mA * N + n] = v0;
            Cb[(size_t)(mA + 1) * N + n] = v1;
        }
    }
}

// ---------------------------------------------------------------------------
// Prep / conversion kernels
// ---------------------------------------------------------------------------
#define NB_WX   8192
#define NB_V    12544
#define NB_EMBX 4864
#define NB_VPW  2048
#define NB_MEGA (NB_WX + NB_V + NB_EMBX + NB_VPW)

__global__ void mega_cvt4(const float* __restrict__ l1_Wih,
                          const float* __restrict__ V,
                          const float* __restrict__ embW,
                          const int* __restrict__ y,
                          const float* __restrict__ Vp_W,
                          __half* __restrict__ WXh, __half* __restrict__ WXl,
                          __half* __restrict__ Vh,  __half* __restrict__ Vl,
                          __half* __restrict__ EXh, __half* __restrict__ EXl,
                          __half* __restrict__ VWh, __half* __restrict__ VWl)
{
    int bid = blockIdx.x;
    if (bid < NB_WX) {
        int idx = bid * 256 + threadIdx.x;
        int r = idx >> 9, c = idx & 511;
        wr_hl16u(WXh, WXl, idx, l1_Wih[(size_t)r * 1536 + c]);
    } else if (bid < NB_WX + NB_V) {
        int idx = (bid - NB_WX) * 256 + threadIdx.x;
        wr_hl16u(Vh, Vl, idx, V[idx]);
    } else if (bid < NB_WX + NB_V + NB_EMBX) {
        int idx = (bid - NB_WX - NB_V) * 256 + threadIdx.x;
        int e = idx & 511;
        int b = (idx >> 9) & 127;
        int t = idx >> 16;
        wr_hl16u(EXh, EXl, idx, embW[(size_t)y[b * TT + t] * EMB + e]);
    } else {
        int idx = (bid - NB_WX - NB_V - NB_EMBX) * 256 + threadIdx.x;
        wr_hl16u(VWh, VWl, idx, Vp_W[idx]);
    }
}

__global__ void cvt_hl(const float* __restrict__ src, int ld, int rows, int cols,
                       __half* __restrict__ hi, __half* __restrict__ lo, int rowsPad)
{
    int idx = blockIdx.x * 256 + threadIdx.x;
    if (idx >= rowsPad * cols) return;
    int r = idx / cols, c = idx - r * cols;
    float x = (r < rows) ? src[(size_t)r * ld + c] : 0.f;
    wr_hl16u(hi, lo, idx, x);
}

__global__ void cvt_h(const float* __restrict__ src, int ld, int rows, int cols,
                      __half* __restrict__ dst, int rowsPad)
{
    int idx = blockIdx.x * 256 + threadIdx.x;
    if (idx >= rowsPad * cols) return;
    int r = idx / cols, c = idx - r * cols;
    float x = (r < rows) ? src[(size_t)r * ld + c] : 0.f;
    dst[idx] = __float2half(x);
}

__global__ void build_wcat_hl(__half* __restrict__ hi, __half* __restrict__ lo,
                              const float* __restrict__ Wih, int ld_ih, int coff,
                              const float* __restrict__ Whh)
{
    int idx = blockIdx.x * 256 + threadIdx.x;
    if (idx >= G4 * 2048) return;
    int n = idx >> 11, k = idx & 2047;
    float x = (k < 1024) ? Wih[(size_t)n * ld_ih + coff + k]
                         : Whh[(size_t)n * 1024 + (k - 1024)];
    wr_hl16u(hi, lo, idx, x);
}

__global__ void add_bias_kernel(float* __restrict__ dst, const float* __restrict__ a,
                                const float* __restrict__ b, int n)
{
    int i = blockIdx.x * 256 + threadIdx.x;
    if (i < n) dst[i] = a[i] + b[i];
}

__global__ void feat_mean_kernel(const float* __restrict__ Vp, float* __restrict__ fm)
{
    int idx = blockIdx.x * 256 + threadIdx.x;
    if (idx >= BB * HD) return;
    int b = idx >> 10, h = idx & 1023;
    const float* p = Vp + (size_t)b * NN * HD + h;
    float s = 0.f;
#pragma unroll 7
    for (int n = 0; n < NN; n++) s += p[n * HD];
    fm[idx] = s * (1.f / 49.f);
}

// ---------------------------------------------------------------------------
// Attention: sums WHZ wh partials, warp softmax, ctx; X1=[ctx|h1] hi/lo
// ---------------------------------------------------------------------------
__global__ void attn_kernel(const float* __restrict__ Vp, const float* __restrict__ Uv,
                            const float* __restrict__ whp, const float* __restrict__ attv,
                            const float* __restrict__ h1cur,
                            __half* __restrict__ x1h, __half* __restrict__ x1l)
{
    int b = blockIdx.x, tid = threadIdx.x;
    __shared__ float s_wh[ATT];
    __shared__ float s_e[NN];

    for (int a = tid; a < ATT; a += 256) {
        int o = b * ATT + a;
        float s = 0.f;
#pragma unroll
        for (int z = 0; z < WHZ; z++) s += whp[z * BB * ATT + o];
        s_wh[a] = s;
    }
    __syncthreads();

    int warp = tid >> 5, lane = tid & 31;
    for (int n = warp; n < NN; n += 8) {
        const float* uv = Uv + ((size_t)b * NN + n) * ATT;
        float s = 0.f;
        for (int a = lane; a < ATT; a += 32) s += tanhf(s_wh[a] + uv[a]) * attv[a];
#pragma unroll
        for (int o = 16; o > 0; o >>= 1) s += __shfl_down_sync(0xffffffffu, s, o);
        if (lane == 0) s_e[n] = s;
    }
    __syncthreads();

    if (warp == 0) {
        float m = -1e30f;
        for (int n = lane; n < NN; n += 32) m = fmaxf(m, s_e[n]);
#pragma unroll
        for (int o = 16; o > 0; o >>= 1) m = fmaxf(m, __shfl_xor_sync(0xffffffffu, m, o));
        float S = 0.f;
        float v0 = 0.f, v1 = 0.f;
        if (lane < NN) { v0 = expf(s_e[lane] - m); S += v0; }
        if (lane + 32 < NN) { v1 = expf(s_e[lane + 32] - m); S += v1; }
#pragma unroll
        for (int o = 16; o > 0; o >>= 1) S += __shfl_xor_sync(0xffffffffu, S, o);
        float inv = 1.f / S;
        if (lane < NN) s_e[lane] = v0 * inv;
        if (lane + 32 < NN) s_e[lane + 32] = v1 * inv;
    }
    __syncthreads();

    const float* vpb = Vp + (size_t)b * NN * HD;
    for (int h = tid; h < HD; h += 256) {
        float acc = 0.f;
#pragma unroll 7
        for (int n = 0; n < NN; n++) acc += s_e[n] * vpb[n * HD + h];
        wr_hl16u(x1h, x1l, (size_t)b * 2048 + h, acc);
    }
    for (int h = tid; h < HD; h += 256)
        wr_hl16u(x1h, x1l, (size_t)b * 2048 + 1024 + h, h1cur[b * HD + h]);
}

// ---------------------------------------------------------------------------
// LSTM cell + LN fused with splitK (ZK) gate reduction — 512 threads
// ---------------------------------------------------------------------------
__global__ void __launch_bounds__(512)
lstm_ln_kernel(const float* __restrict__ gp, const float* __restrict__ bias,
               const float* __restrict__ extra,
               const float* __restrict__ cin, float* __restrict__ cout,
               const float* __restrict__ gam, const float* __restrict__ bet,
               float* __restrict__ hout,
               __half* __restrict__ x2h, __half* __restrict__ x2l,
               const float* __restrict__ h2cur)
{
    const size_t BG = (size_t)BB * G4;
    int b = blockIdx.x, tid = threadIdx.x;
    __shared__ float s_h[HD];
    __shared__ float s_red[64];
    __shared__ float s_mu, s_rstd;

    float sum = 0.f, sq = 0.f;
    for (int h = tid; h < HD; h += 512) {
        float g[4];
#pragma unroll
        for (int q = 0; q < 4; q++) {
            size_t idx = (size_t)b * G4 + q * 1024 + h;
            float v = bias[q * 1024 + h];
#pragma unroll
            for (int z = 0; z < ZK; z++) v += gp[z * BG + idx];
            if (extra) v += extra[idx];
            g[q] = v;
        }
        float c = sigf(g[1]) * cin[b * HD + h] + sigf(g[0]) * tanhf(g[2]);
        cout[b * HD + h] = c;
        float hv = sigf(g[3]) * tanhf(c);
        s_h[h] = hv;
        sum += hv; sq += hv * hv;
    }
#pragma unroll
    for (int o = 16; o > 0; o >>= 1) {
        sum += __shfl_down_sync(0xffffffffu, sum, o);
        sq  += __shfl_down_sync(0xffffffffu, sq,  o);
    }
    int warp = tid >> 5, lane = tid & 31;
    if (lane == 0) { s_red[warp] = sum; s_red[32 + warp] = sq; }
    __syncthreads();
    if (tid == 0) {
        float S = 0.f, Q = 0.f;
        for (int w = 0; w < 16; w++) { S += s_red[w]; Q += s_red[32 + w]; }
        float mu = S * (1.f / 1024.f);
        float var = Q * (1.f / 1024.f) - mu * mu;
        s_mu = mu; s_rstd = 1.f / sqrtf(var + 1e-5f);
    }
    __syncthreads();
    float mu = s_mu, rstd = s_rstd;
    for (int h = tid; h < HD; h += 512) {
        float v = (s_h[h] - mu) * rstd * gam[h] + bet[h];
        hout[b * HD + h] = v;
        if (x2h) wr_hl16u(x2h, x2l, (size_t)b * 2048 + h, v);
    }
    if (x2h)
        for (int h = tid; h < HD; h += 512)
            wr_hl16u(x2h, x2l, (size_t)b * 2048 + 1024 + h, h2cur[b * HD + h]);
}

// ---------------------------------------------------------------------------
// Launch
// ---------------------------------------------------------------------------
extern "C" void kernel_launch(void* const* d_in, const int* in_sizes, int n_in,
                              void* d_out, int out_size)
{
    (void)in_sizes; (void)n_in; (void)out_size;
    const float* V      = (const float*)d_in[0];
    const int*   y      = (const int*)  d_in[1];
    const float* embW   = (const float*)d_in[2];
    const float* Vp_W   = (const float*)d_in[3];
    const float* Vp_b   = (const float*)d_in[4];
    const float* attW   = (const float*)d_in[5];
    const float* attU   = (const float*)d_in[6];
    const float* attv   = (const float*)d_in[7];
    const float* l1_Wih = (const float*)d_in[8];
    const float* l1_Whh = (const float*)d_in[9];
    const float* l1_bih = (const float*)d_in[10];
    const float* l1_bhh = (const float*)d_in[11];
    const float* l2_Wih = (const float*)d_in[12];
    const float* l2_Whh = (const float*)d_in[13];
    const float* l2_bih = (const float*)d_in[14];
    const float* l2_bhh = (const float*)d_in[15];
    const float* n1_g   = (const float*)d_in[16];
    const float* n1_b   = (const float*)d_in[17];
    const float* n2_g   = (const float*)d_in[18];
    const float* n2_b   = (const float*)d_in[19];
    const float* ih_W   = (const float*)d_in[20];
    const float* ih_b   = (const float*)d_in[21];
    const float* ic_W   = (const float*)d_in[22];
    const float* ic_b   = (const float*)d_in[23];
    const float* proj_W = (const float*)d_in[24];
    float* out = (float*)d_out;

    cudaFuncSetAttribute(hmma_gemm<0, 1, 1>, cudaFuncAttributeMaxDynamicSharedMemorySize, HM_SMEM4);
    cudaFuncSetAttribute(hmma_gemm<0, 0, 0>, cudaFuncAttributeMaxDynamicSharedMemorySize, HM_SMEM2);
    cudaFuncSetAttribute(hmma_gemm<3, 0, 0>, cudaFuncAttributeMaxDynamicSharedMemorySize, HM_SMEM2);

    float* buf = nullptr;
    cudaGetSymbolAddress((void**)&buf, g_buf);
    __half* hf = nullptr;
    cudaGetSymbolAddress((void**)&hf, g_hf);

    float* VP  = buf + OFF_VP;
    float* UV  = buf + OFF_UV;
    float* FM  = buf + OFF_FM;
    float* H1  = buf + OFF_H1;
    float* C1  = buf + OFF_C1;
    float* C2  = buf + OFF_C2;
    float* H2A = buf + OFF_H2A;
    float* G1X = buf + OFF_G1X;
    float* B1  = buf + OFF_B1;
    float* B2  = buf + OFF_B2;
    float* GP  = buf + OFF_GP;
    float* WHP = buf + OFF_WHP;
    float* PF  = buf + OFF_PF;

    __half *W1h = hf + HO_W1,   *W1l = W1h + SZ_W1;      // hi/lo (3-pass)
    __half *W2h = hf + HO_W2,   *W2l = W2h + SZ_W2;      // hi/lo (3-pass)
    __half *EWs = hf + HO_EMBW;                          // single (1-pass logits)
    __half *PJh = hf + HO_PROJ, *PJl = PJh + SZ_PROJ;    // hi/lo (3-pass)
    __half *AUs = hf + HO_ATTU;                          // single (1-pass Uv)
    __half *VWh = hf + HO_VPW,  *VWl = VWh + SZ_VPW;     // hi/lo (3-pass)
    __half *WXh = hf + HO_WX,   *WXl = WXh + SZ_WX;      // hi/lo (3-pass)
    __half *Vh  = hf + HO_V,    *Vl  = Vh  + SZ_V;
    __half *VPs = hf + HO_VPB;                           // single (1-pass Uv)
    __half *EXh = hf + HO_EMBX, *EXl = EXh + SZ_EMBX;
    __half *X1h = hf + HO_X1,   *X1l = X1h + SZ_X1;
    __half *X2h = hf + HO_X2,   *X2l = X2h + SZ_X2;
    __half *H2h = hf + HO_H2,   *H2l = H2h + SZ_H2;
    __half *Ps  = hf + HO_P;                             // single (1-pass logits)

    const int SLOT = BB * HD;
    auto nb = [](size_t tot) { return (unsigned)((tot + 255) / 256); };

    // ---- launch #1: fused conversion of critical-path operands ----
    mega_cvt4<<<NB_MEGA, 256>>>(l1_Wih, V, embW, y, Vp_W,
                                WXh, WXl, Vh, Vl, EXh, EXl, VWh, VWl);
    // launches #2..#4: hmma GEMMs (ncu capture window)
    hmma_gemm<0, 1, 1><<<dim3(G4 / 128, 10, 1), 512, HM_SMEM4>>>(EXh, EXl, EMB, WXh, WXl, EMB,
                                                                 G1X, G4, EMB, nullptr);
    hmma_gemm<0, 1, 1><<<dim3(G4 / 128, 9, 1), 512, HM_SMEM4>>>(EXh + (size_t)1280 * EMB,
                                                                EXl + (size_t)1280 * EMB, EMB,
                                                                WXh, WXl, EMB,
                                                                G1X + (size_t)1280 * G4, G4, EMB,
                                                                nullptr);
    hmma_gemm<0, 1, 1><<<dim3(HD / 128, NN, 1), 512, HM_SMEM4>>>(Vh, Vl, VD, VWh, VWl, VD,
                                                                 VP, HD, VD, Vp_b);

    build_wcat_hl<<<nb((size_t)G4 * 2048), 256>>>(W1h, W1l, l1_Wih, 1536, 512, l1_Whh);
    build_wcat_hl<<<nb((size_t)G4 * 2048), 256>>>(W2h, W2l, l2_Wih, 1024, 0, l2_Whh);
    cvt_h<<<nb((size_t)NVP * EMB), 256>>>(embW, EMB, VOCAB, EMB, EWs, NVP);
    cvt_hl<<<nb(SZ_PROJ), 256>>>(proj_W, HD, EMB, HD, PJh, PJl, EMB);
    cvt_h<<<nb(SZ_ATTU), 256>>>(attU, HD, ATT, HD, AUs, ATT);
    add_bias_kernel<<<32, 256>>>(B1, l1_bih, l1_bhh, G4);
    add_bias_kernel<<<32, 256>>>(B2, l2_bih, l2_bhh, G4);

    cvt_h<<<nb(SZ_VPB), 256>>>(VP, HD, BB * NN, HD, VPs, BB * NN);
    feat_mean_kernel<<<nb((size_t)BB * HD), 256>>>(VP, FM);
    gemm_tile<1><<<dim3(HD / 32, 1, 1), 128>>>(FM, HD, ih_W, HD, H1, HD, HD, ih_b);
    gemm_tile<1><<<dim3(HD / 32, 1, 1), 128>>>(FM, HD, ic_W, HD, C1, HD, HD, ic_b);
    // Uv (1-pass; softmax-damped): Vp @ attU^T
    hmma_gemm<0, 0, 0><<<dim3(ATT / 128, NN, 1), 512, HM_SMEM2>>>(VPs, nullptr, HD, AUs, nullptr,
                                                                  HD, UV, ATT, HD, nullptr);

    cudaMemsetAsync(H2A, 0, (size_t)SLOT * sizeof(float), 0);
    cudaMemsetAsync(C2, 0, (size_t)SLOT * sizeof(float), 0);

    // ---- sequential decode ----
    for (int t = 0; t < TS; t++) {
        const float* h2c = H2A + (size_t)t * SLOT;
        gemm_tile<0><<<dim3(ATT / 32, 1, WHZ), 128>>>(h2c, HD, attW, HD, WHP, ATT, HD, nullptr);
        attn_kernel<<<BB, 256>>>(VP, UV, WHP, attv, H1 + (size_t)(t & 1) * SLOT, X1h, X1l);
        hmma_gemm<0, 1, 1><<<dim3(G4 / 128, 1, ZK), 512, HM_SMEM4>>>(X1h, X1l, 2048, W1h, W1l,
                                                                     2048, GP, G4, 2048, nullptr);
        lstm_ln_kernel<<<BB, 512>>>(GP, B1, G1X + (size_t)t * BB * G4,
                                    C1 + (size_t)(t & 1) * SLOT,
                                    C1 + (size_t)((t + 1) & 1) * SLOT,
                                    n1_g, n1_b, H1 + (size_t)((t + 1) & 1) * SLOT,
                                    X2h, X2l, h2c);
        hmma_gemm<0, 1, 1><<<dim3(G4 / 128, 1, ZK), 512, HM_SMEM4>>>(X2h, X2l, 2048, W2h, W2l,
                                                                     2048, GP, G4, 2048, nullptr);
        lstm_ln_kernel<<<BB, 512>>>(GP, B2, nullptr,
                                    C2 + (size_t)(t & 1) * SLOT,
                                    C2 + (size_t)((t + 1) & 1) * SLOT,
                                    n2_g, n2_b, H2A + (size_t)(t + 1) * SLOT,
                                    nullptr, nullptr, nullptr);
    }

    // ---- deferred output projection (proj 3-pass, logits 1-pass) ----
    cvt_hl<<<nb(SZ_H2), 256>>>(H2A + SLOT, HD, TS * BB, HD, H2h, H2l, TS * BB);
    hmma_gemm<0, 1, 1><<<dim3(EMB / 128, TS, 1), 512, HM_SMEM4>>>(H2h, H2l, HD, PJh, PJl, HD,
                                                                  PF, EMB, HD, nullptr);
    cvt_h<<<nb(SZ_P), 256>>>(PF, EMB, TS * BB, EMB, Ps, TS * BB);
    hmma_gemm<3, 0, 0><<<dim3(NVP / 128, TS, 1), 512, HM_SMEM2>>>(Ps, nullptr, EMB, EWs, nullptr,
                                                                  EMB, out, VOCAB, EMB, nullptr);
}